// round 1
// baseline (speedup 1.0000x reference)
#include <cuda_runtime.h>
#include <math.h>

// Problem constants (fixed by setup_inputs)
#define N 8192
#define D 512
#define TEMP_INV 10.0f   // 1 / 0.1

// Fused-kernel tiling
#define BM 64
#define BN 128
#define BK 16
#define TPB 128

// Normalized X scratch (16 MB) — static device array (allowed; fits in L2)
__device__ float g_Xn[N * D];

// ---------------------------------------------------------------------------
// Kernel 1: L2-normalize rows.  One warp per row.
// ---------------------------------------------------------------------------
__global__ void normalize_kernel(const float* __restrict__ X) {
    int row  = blockIdx.x * 8 + (threadIdx.x >> 5);
    int lane = threadIdx.x & 31;

    const float4* src = reinterpret_cast<const float4*>(X + (size_t)row * D);
    float4*       dst = reinterpret_cast<float4*>(g_Xn + (size_t)row * D);

    float4 v[4];
    float s = 0.0f;
#pragma unroll
    for (int i = 0; i < 4; i++) {
        v[i] = src[i * 32 + lane];
        s += v[i].x * v[i].x + v[i].y * v[i].y + v[i].z * v[i].z + v[i].w * v[i].w;
    }
#pragma unroll
    for (int off = 16; off; off >>= 1)
        s += __shfl_xor_sync(0xffffffffu, s, off);

    float scale = 1.0f / fmaxf(sqrtf(s), 1e-12f);
#pragma unroll
    for (int i = 0; i < 4; i++) {
        v[i].x *= scale; v[i].y *= scale; v[i].z *= scale; v[i].w *= scale;
        dst[i * 32 + lane] = v[i];
    }
}

// ---------------------------------------------------------------------------
// Kernel 2: fused  sim = Xn Xn^T  +  per-row top-5  +  softmax scatter.
// Grid: N/BM = 128 blocks, 128 threads each.  Block owns rows
// [rowBase, rowBase+64); loops over 64 column tiles of 128.
// ---------------------------------------------------------------------------
__global__ __launch_bounds__(TPB, 1) void fused_kernel(float* __restrict__ out) {
    __shared__ float As[BK][BM + 1];    // [16][65]  k-major, pad 1 -> conflict-free
    __shared__ float Bs[BK][BN + 4];    // [16][132] k-major, pad 4 -> float4 reads
    __shared__ float Cs[BM][BN + 1];    // [64][129] staging for top-k scan

    const int tid = threadIdx.x;
    const int tx  = tid & 15;           // 0..15 -> 8 columns each
    const int ty  = tid >> 4;           // 0..7  -> 8 rows each
    const int rowBase = blockIdx.x * BM;

    // ---- zero this block's output rows (overlaps with compute below) ----
    {
        float4 z = make_float4(0.f, 0.f, 0.f, 0.f);
        float4* o4 = reinterpret_cast<float4*>(out + (size_t)rowBase * N);
        const int total = BM * N / 4;                    // 131072 float4
        for (int i = tid; i < total; i += TPB) o4[i] = z;
    }

    // ---- per-row top-5 state (threads 0..63 each own one row) ----
    float tv0 = -1e30f, tv1 = -1e30f, tv2 = -1e30f, tv3 = -1e30f, tv4 = -1e30f;
    int   ti0 = 0, ti1 = 0, ti2 = 0, ti3 = 0, ti4 = 0;

    for (int ct = 0; ct < N / BN; ct++) {
        const int colBase = ct * BN;

        float acc[8][8];
#pragma unroll
        for (int r = 0; r < 8; r++)
#pragma unroll
            for (int c = 0; c < 8; c++) acc[r][c] = 0.0f;

        for (int kc = 0; kc < D / BK; kc++) {
            __syncthreads();   // previous tile's smem readers done

            // load A tile: 64 rows x 16 k  (256 float4, 2 per thread)
#pragma unroll
            for (int i = 0; i < 2; i++) {
                int L  = tid + i * TPB;
                int r  = L >> 2;
                int kq = L & 3;
                float4 f = *reinterpret_cast<const float4*>(
                    &g_Xn[(size_t)(rowBase + r) * D + kc * BK + kq * 4]);
                As[kq * 4 + 0][r] = f.x;
                As[kq * 4 + 1][r] = f.y;
                As[kq * 4 + 2][r] = f.z;
                As[kq * 4 + 3][r] = f.w;
            }
            // load B tile: 128 rows x 16 k (512 float4, 4 per thread)
#pragma unroll
            for (int i = 0; i < 4; i++) {
                int L  = tid + i * TPB;
                int r  = L >> 2;
                int kq = L & 3;
                float4 f = *reinterpret_cast<const float4*>(
                    &g_Xn[(size_t)(colBase + r) * D + kc * BK + kq * 4]);
                Bs[kq * 4 + 0][r] = f.x;
                Bs[kq * 4 + 1][r] = f.y;
                Bs[kq * 4 + 2][r] = f.z;
                Bs[kq * 4 + 3][r] = f.w;
            }
            __syncthreads();

#pragma unroll
            for (int k = 0; k < BK; k++) {
                float a[8], b[8];
#pragma unroll
                for (int r = 0; r < 8; r++) a[r] = As[k][ty * 8 + r];
                float4 b0 = *reinterpret_cast<const float4*>(&Bs[k][tx * 8]);
                float4 b1 = *reinterpret_cast<const float4*>(&Bs[k][tx * 8 + 4]);
                b[0] = b0.x; b[1] = b0.y; b[2] = b0.z; b[3] = b0.w;
                b[4] = b1.x; b[5] = b1.y; b[6] = b1.z; b[7] = b1.w;
#pragma unroll
                for (int r = 0; r < 8; r++)
#pragma unroll
                    for (int c = 0; c < 8; c++)
                        acc[r][c] = fmaf(a[r], b[c], acc[r][c]);
            }
        }

        // ---- stage C tile to shared ----
#pragma unroll
        for (int r = 0; r < 8; r++)
#pragma unroll
            for (int c = 0; c < 8; c++)
                Cs[ty * 8 + r][tx * 8 + c] = acc[r][c];
        __syncthreads();

        // ---- top-5 scan: thread tid (<64) owns row rowBase+tid ----
        if (tid < BM) {
            for (int j = 0; j < BN; j++) {
                float v   = Cs[tid][j];
                int   idx = colBase + j;
                // strict > with ascending index scan == jax.lax.top_k tie rule
                if (v > tv4) {
                    if (v > tv3) {
                        tv4 = tv3; ti4 = ti3;
                        if (v > tv2) {
                            tv3 = tv2; ti3 = ti2;
                            if (v > tv1) {
                                tv2 = tv1; ti2 = ti1;
                                if (v > tv0) {
                                    tv1 = tv0; ti1 = ti0;
                                    tv0 = v;  ti0 = idx;
                                } else { tv1 = v; ti1 = idx; }
                            } else { tv2 = v; ti2 = idx; }
                        } else { tv3 = v; ti3 = idx; }
                    } else { tv4 = v; ti4 = idx; }
                }
            }
        }
        // Cs is only rewritten after the next full kc loop (which has syncs),
        // so scanners are protected without an extra barrier here.
    }

    // ---- softmax over the 5 kept logits, scatter into zeroed row ----
    if (tid < BM) {
        float m  = tv0;                              // max (diag = 1.0 is always top-1)
        float e0 = expf((tv0 - m) * TEMP_INV);
        float e1 = expf((tv1 - m) * TEMP_INV);
        float e2 = expf((tv2 - m) * TEMP_INV);
        float e3 = expf((tv3 - m) * TEMP_INV);
        float e4 = expf((tv4 - m) * TEMP_INV);
        float inv = 1.0f / (e0 + e1 + e2 + e3 + e4);

        float* orow = out + (size_t)(rowBase + tid) * N;
        orow[ti0] = e0 * inv;
        orow[ti1] = e1 * inv;
        orow[ti2] = e2 * inv;
        orow[ti3] = e3 * inv;
        orow[ti4] = e4 * inv;
    }
}

// ---------------------------------------------------------------------------
extern "C" void kernel_launch(void* const* d_in, const int* in_sizes, int n_in,
                              void* d_out, int out_size) {
    (void)in_sizes; (void)n_in; (void)out_size;
    const float* X   = (const float*)d_in[0];
    float*       out = (float*)d_out;

    normalize_kernel<<<N / 8, 256>>>(X);
    fused_kernel<<<N / BM, TPB>>>(out);
}

// round 3
// speedup vs baseline: 5.5919x; 5.5919x over previous
#include <cuda_runtime.h>
#include <cuda_bf16.h>
#include <cstdint>
#include <math.h>

#define N 8192
#define D 512
#define TEMP_INV 10.0f

#define TILE_M 128
#define TILE_N 128
#define NTILES 32          // column tiles per CTA (4096/128)
#define TPB    256

// ---- device scratch (static; no allocations allowed) ----
__device__ float          g_Xn[N * D];     // 16 MB fp32 normalized (rescore)
__device__ __nv_bfloat16  g_Xb[N * D];     // 8 MB bf16 normalized (GEMM)
__device__ int            g_cand_idx[N * 16];

// ---- SMEM byte offsets (dynamic) ----
// A: 8 chunks x [128 rows][64 k] bf16, XOR-swizzled, 16KB each = 128KB
// B: two buffers [128][64] bf16 = 16KB each
// C: [128][128] f32, column-XOR-swizzled = 64KB
#define SM_A   0
#define SM_B0  131072
#define SM_B1  147456
#define SM_C   163840
#define SMEM_TOTAL 229376   // 224 KB (< 227 KB limit)

// ================= helpers =================
__device__ __forceinline__ uint32_t smem_u32(const void* p) {
    uint32_t a;
    asm("{ .reg .u64 t; cvta.to.shared.u64 t, %1; cvt.u32.u64 %0, t; }" : "=r"(a) : "l"(p));
    return a;
}
__device__ __forceinline__ void ldsm4(uint32_t* r, uint32_t addr) {
    asm volatile("ldmatrix.sync.aligned.m8n8.x4.shared.b16 {%0,%1,%2,%3}, [%4];"
                 : "=r"(r[0]), "=r"(r[1]), "=r"(r[2]), "=r"(r[3]) : "r"(addr));
}
__device__ __forceinline__ void mma16816(float* c, const uint32_t* a, const uint32_t* b) {
    asm volatile("mma.sync.aligned.m16n8k16.row.col.f32.bf16.bf16.f32 "
                 "{%0,%1,%2,%3}, {%4,%5,%6,%7}, {%8,%9}, {%0,%1,%2,%3};"
                 : "+f"(c[0]), "+f"(c[1]), "+f"(c[2]), "+f"(c[3])
                 : "r"(a[0]), "r"(a[1]), "r"(a[2]), "r"(a[3]), "r"(b[0]), "r"(b[1]));
}

// ===========================================================================
// Kernel 1: L2-normalize rows -> fp32 + bf16.  One warp per row.
// ===========================================================================
__global__ void normalize_kernel(const float* __restrict__ X) {
    int row  = blockIdx.x * 8 + (threadIdx.x >> 5);
    int lane = threadIdx.x & 31;
    const float4* src = reinterpret_cast<const float4*>(X + (size_t)row * D);

    float4 v[4];
    float s = 0.0f;
#pragma unroll
    for (int i = 0; i < 4; i++) {
        v[i] = src[i * 32 + lane];
        s += v[i].x*v[i].x + v[i].y*v[i].y + v[i].z*v[i].z + v[i].w*v[i].w;
    }
#pragma unroll
    for (int o = 16; o; o >>= 1) s += __shfl_xor_sync(0xffffffffu, s, o);
    float scale = 1.0f / fmaxf(sqrtf(s), 1e-12f);

    float4* dst = reinterpret_cast<float4*>(g_Xn + (size_t)row * D);
    __nv_bfloat162* db = reinterpret_cast<__nv_bfloat162*>(g_Xb + (size_t)row * D);
#pragma unroll
    for (int i = 0; i < 4; i++) {
        v[i].x *= scale; v[i].y *= scale; v[i].z *= scale; v[i].w *= scale;
        dst[i * 32 + lane] = v[i];
        db[i * 64 + lane * 2 + 0] = __nv_bfloat162(__float2bfloat16(v[i].x), __float2bfloat16(v[i].y));
        db[i * 64 + lane * 2 + 1] = __nv_bfloat162(__float2bfloat16(v[i].z), __float2bfloat16(v[i].w));
    }
}

// ===========================================================================
// Kernel 2: bf16 HMMA GEMM (fp32 accum) + per-row top-8 + zero-fill overlap.
// 128 CTAs = 64 M-tiles x 2 N-halves, 256 threads (8 warps; warp = 32x64).
// ===========================================================================
__global__ __launch_bounds__(TPB, 1) void fused_mma(float* __restrict__ out) {
    extern __shared__ char smem[];
    const uint32_t sb = smem_u32(smem);
    float* Cs = reinterpret_cast<float*>(smem + SM_C);

    const int tid = threadIdx.x, wid = tid >> 5, lane = tid & 31;
    const int mtile = blockIdx.x >> 1, half = blockIdx.x & 1;
    const int rowBase = mtile * TILE_M, colHalf = half * 4096;
    const int wr = wid >> 1, wc = wid & 1;     // warp 32-row band, 64-col band

    // ---- resident A tile: 128 x 512 bf16, swizzled, 8 chunks of [128][64] ----
#pragma unroll
    for (int i = 0; i < 32; i++) {
        int lin = tid + i * TPB;
        int r = lin >> 6, seg = lin & 63;              // seg = k/8 over full row
        uint4 v = *reinterpret_cast<const uint4*>(&g_Xb[(size_t)(rowBase + r) * D + seg * 8]);
        uint32_t off = (uint32_t)((seg >> 3) * 16384 + r * 128 + (((seg & 7) ^ (r & 7)) << 4));
        *reinterpret_cast<uint4*>(smem + SM_A + off) = v;
    }

    float tv[8]; int ti[8];
#pragma unroll
    for (int j = 0; j < 8; j++) { tv[j] = -1e30f; ti[j] = 0; }

    // ldmatrix lane -> (row, k8) offsets
    const int grp = lane >> 3, l7 = lane & 7;
    const int a_r  = ((grp & 1) << 3) | l7;   // A x4: m0 r0-7,k0; m1 r8-15,k0; m2 r0-7,k8; m3 r8-15,k8
    const int a_k8 = grp >> 1;
    const int b_n  = ((grp >> 1) << 3) | l7;  // B x4: m0 n0-7,k0; m1 n0-7,k8; m2 n8-15,k0; m3 n8-15,k8
    const int b_k8 = grp & 1;

    for (int t = 0; t < NTILES; t++) {
        const int colBase = colHalf + t * TILE_N;

        // load B chunk kc=0 into buf0
#pragma unroll
        for (int i = 0; i < 4; i++) {
            int lin = tid + i * TPB;
            int r = lin >> 3, seg = lin & 7;
            uint4 v = *reinterpret_cast<const uint4*>(&g_Xb[(size_t)(colBase + r) * D + seg * 8]);
            *reinterpret_cast<uint4*>(smem + SM_B0 + r * 128 + ((seg ^ (r & 7)) << 4)) = v;
        }
        __syncthreads();

        float acc[2][8][4];
#pragma unroll
        for (int mf = 0; mf < 2; mf++)
#pragma unroll
            for (int nf = 0; nf < 8; nf++)
#pragma unroll
                for (int ri = 0; ri < 4; ri++) acc[mf][nf][ri] = 0.0f;

        for (int kc = 0; kc < 8; kc++) {
            uint4 v[4];
            if (kc < 7) {
#pragma unroll
                for (int i = 0; i < 4; i++) {
                    int lin = tid + i * TPB;
                    int r = lin >> 3, seg = lin & 7;
                    v[i] = *reinterpret_cast<const uint4*>(
                        &g_Xb[(size_t)(colBase + r) * D + (kc + 1) * 64 + seg * 8]);
                }
            }
            const uint32_t abase = sb + SM_A + kc * 16384;
            const uint32_t bbase = sb + ((kc & 1) ? SM_B1 : SM_B0);

#pragma unroll
            for (int ks = 0; ks < 4; ks++) {
                const int kb8 = ks * 2;
                uint32_t a0[4], a1[4];
                {
                    int r0 = wr * 32 + a_r;
                    ldsm4(a0, abase + r0 * 128 + (((kb8 + a_k8) ^ (r0 & 7)) << 4));
                    int r1 = r0 + 16;
                    ldsm4(a1, abase + r1 * 128 + (((kb8 + a_k8) ^ (r1 & 7)) << 4));
                }
                uint32_t bfr[4][4];
#pragma unroll
                for (int q = 0; q < 4; q++) {
                    int n = wc * 64 + q * 16 + b_n;
                    ldsm4(bfr[q], bbase + n * 128 + (((kb8 + b_k8) ^ (n & 7)) << 4));
                }
#pragma unroll
                for (int nf = 0; nf < 8; nf++) {
                    mma16816(acc[0][nf], a0, &bfr[nf >> 1][(nf & 1) * 2]);
                    mma16816(acc[1][nf], a1, &bfr[nf >> 1][(nf & 1) * 2]);
                }
            }

            if (kc < 7) {
#pragma unroll
                for (int i = 0; i < 4; i++) {
                    int lin = tid + i * TPB;
                    int r = lin >> 3, seg = lin & 7;
                    *reinterpret_cast<uint4*>(
                        smem + ((kc & 1) ? SM_B0 : SM_B1) + r * 128 + ((seg ^ (r & 7)) << 4)) = v[i];
                }
                __syncthreads();
            }
        }

        // ---- stage C to smem (col XOR row swizzle -> conflict-free scan) ----
#pragma unroll
        for (int mf = 0; mf < 2; mf++)
#pragma unroll
            for (int nf = 0; nf < 8; nf++)
#pragma unroll
                for (int ri = 0; ri < 4; ri++) {
                    int row = wr * 32 + mf * 16 + (lane >> 2) + ((ri >> 1) << 3);
                    int col = wc * 64 + nf * 8 + ((lane & 3) << 1) + (ri & 1);
                    Cs[row * 128 + (col ^ (row & 31))] = acc[mf][nf][ri];
                }
        __syncthreads();

        if (tid < 128) {
            // scan row `tid` of the 128x128 tile; maintain sorted top-8
            const int r = tid, rx = r & 31;
            const float* crow = Cs + r * 128;
#pragma unroll 4
            for (int c = 0; c < 128; c++) {
                float v = crow[c ^ rx];
                if (v > tv[7]) {
                    int idx = colBase + c;
                    tv[7] = v; ti[7] = idx;
#pragma unroll
                    for (int p = 7; p > 0; p--) {
                        if (tv[p] > tv[p - 1]) {
                            float fv = tv[p]; tv[p] = tv[p - 1]; tv[p - 1] = fv;
                            int   fi = ti[p]; ti[p] = ti[p - 1]; ti[p - 1] = fi;
                        }
                    }
                }
            }
        } else {
            // zero-fill 64 KB of this CTA's output region
            const float4 z = make_float4(0.f, 0.f, 0.f, 0.f);
            const int base = tid - 128;
#pragma unroll
            for (int i = 0; i < 32; i++) {
                int gi = t * 4096 + base + i * 128;    // float4 index within 128x1024-f4 region
                int r = gi >> 10, c = gi & 1023;
                *reinterpret_cast<float4*>(out + (size_t)(rowBase + r) * N + colHalf + c * 4) = z;
            }
        }
        __syncthreads();
    }

    if (tid < 128) {
        int row = rowBase + tid;
#pragma unroll
        for (int j = 0; j < 8; j++) g_cand_idx[row * 16 + half * 8 + j] = ti[j];
    }
}

// ===========================================================================
// Kernel 3: exact fp32 rescore of 16 candidates/row, top-5 (jax tie rule),
// softmax, scatter.  One warp per row.
// ===========================================================================
__global__ __launch_bounds__(256) void rescore_kernel(float* __restrict__ out) {
    const int wid = threadIdx.x >> 5, lane = threadIdx.x & 31;
    const int row = blockIdx.x * 8 + wid;

    float xr[16];
#pragma unroll
    for (int i = 0; i < 16; i++) xr[i] = g_Xn[(size_t)row * D + i * 32 + lane];

    float myv = -1e30f; int myi = 0x7fffffff;
#pragma unroll
    for (int c = 0; c < 16; c++) {
        int idx = g_cand_idx[row * 16 + c];
        const float* Xc = g_Xn + (size_t)idx * D;
        float s = 0.f;
#pragma unroll
        for (int i = 0; i < 16; i++) s = fmaf(xr[i], Xc[i * 32 + lane], s);
#pragma unroll
        for (int o = 16; o; o >>= 1) s += __shfl_xor_sync(0xffffffffu, s, o);
        if (lane == c) { myv = s; myi = idx; }
    }

    float sv[5]; int si[5];
#pragma unroll
    for (int r5 = 0; r5 < 5; r5++) {
        float v = myv; int i = myi;
#pragma unroll
        for (int o = 16; o; o >>= 1) {
            float ov = __shfl_xor_sync(0xffffffffu, v, o);
            int   oi = __shfl_xor_sync(0xffffffffu, i, o);
            if (ov > v || (ov == v && oi < i)) { v = ov; i = oi; }
        }
        sv[r5] = v; si[r5] = i;
        if (myi == i) { myv = -1e30f; myi = 0x7fffffff; }
    }

    if (lane == 0) {
        float m = sv[0];
        float e0 = expf((sv[0] - m) * TEMP_INV);
        float e1 = expf((sv[1] - m) * TEMP_INV);
        float e2 = expf((sv[2] - m) * TEMP_INV);
        float e3 = expf((sv[3] - m) * TEMP_INV);
        float e4 = expf((sv[4] - m) * TEMP_INV);
        float inv = 1.0f / (e0 + e1 + e2 + e3 + e4);
        float* o = out + (size_t)row * N;
        o[si[0]] = e0 * inv; o[si[1]] = e1 * inv; o[si[2]] = e2 * inv;
        o[si[3]] = e3 * inv; o[si[4]] = e4 * inv;
    }
}

// ===========================================================================
extern "C" void kernel_launch(void* const* d_in, const int* in_sizes, int n_in,
                              void* d_out, int out_size) {
    (void)in_sizes; (void)n_in; (void)out_size;
    const float* X   = (const float*)d_in[0];
    float*       out = (float*)d_out;

    cudaFuncSetAttribute(fused_mma, cudaFuncAttributeMaxDynamicSharedMemorySize, SMEM_TOTAL);

    normalize_kernel<<<N / 8, 256>>>(X);
    fused_mma<<<128, TPB, SMEM_TOTAL>>>(out);
    rescore_kernel<<<N / 8, 256>>>(out);
}

// round 4
// speedup vs baseline: 6.0418x; 1.0805x over previous
#include <cuda_runtime.h>
#include <cuda_bf16.h>
#include <cstdint>
#include <math.h>

#define N 8192
#define D 512
#define TEMP_INV 10.0f

#define TILE_M 128
#define TILE_N 128
#define NTILES 32          // column tiles per CTA (4096/128)
#define TPB    256
#define TK     6           // per-lane top-K per row

// ---- device scratch (static; no allocations allowed) ----
__device__ float          g_Xn[N * D];     // 16 MB fp32 normalized (rescore)
__device__ __nv_bfloat16  g_Xb[N * D];     // 8 MB bf16 normalized (GEMM)
__device__ int            g_cand_idx[N * 16];

// ---- SMEM layout ----
// A: 8 chunks x [128][64] bf16 swizzled = 128KB (reused for candidate merge)
// B: two cp.async buffers [128][64] bf16 = 16KB each
#define SM_A   0
#define SM_B0  131072
#define SM_B1  147456
#define SMEM_TOTAL 163840   // 160 KB

// ================= helpers =================
__device__ __forceinline__ uint32_t smem_u32(const void* p) {
    uint32_t a;
    asm("{ .reg .u64 t; cvta.to.shared.u64 t, %1; cvt.u32.u64 %0, t; }" : "=r"(a) : "l"(p));
    return a;
}
__device__ __forceinline__ void ldsm4(uint32_t* r, uint32_t addr) {
    asm volatile("ldmatrix.sync.aligned.m8n8.x4.shared.b16 {%0,%1,%2,%3}, [%4];"
                 : "=r"(r[0]), "=r"(r[1]), "=r"(r[2]), "=r"(r[3]) : "r"(addr));
}
__device__ __forceinline__ void mma16816(float* c, const uint32_t* a, const uint32_t* b) {
    asm volatile("mma.sync.aligned.m16n8k16.row.col.f32.bf16.bf16.f32 "
                 "{%0,%1,%2,%3}, {%4,%5,%6,%7}, {%8,%9}, {%0,%1,%2,%3};"
                 : "+f"(c[0]), "+f"(c[1]), "+f"(c[2]), "+f"(c[3])
                 : "r"(a[0]), "r"(a[1]), "r"(a[2]), "r"(a[3]), "r"(b[0]), "r"(b[1]));
}
#define CP16(sa, gp) \
    asm volatile("cp.async.cg.shared.global [%0], [%1], 16;" :: "r"(sa), "l"(gp) : "memory")
#define CP_COMMIT()  asm volatile("cp.async.commit_group;" ::: "memory")
#define CP_WAIT0()   asm volatile("cp.async.wait_group 0;" ::: "memory")

// ===========================================================================
// Kernel 1: L2-normalize rows -> fp32 + bf16.  One warp per row.
// ===========================================================================
__global__ void normalize_kernel(const float* __restrict__ X) {
    int row  = blockIdx.x * 8 + (threadIdx.x >> 5);
    int lane = threadIdx.x & 31;
    const float4* src = reinterpret_cast<const float4*>(X + (size_t)row * D);

    float4 v[4];
    float s = 0.0f;
#pragma unroll
    for (int i = 0; i < 4; i++) {
        v[i] = src[i * 32 + lane];
        s += v[i].x*v[i].x + v[i].y*v[i].y + v[i].z*v[i].z + v[i].w*v[i].w;
    }
#pragma unroll
    for (int o = 16; o; o >>= 1) s += __shfl_xor_sync(0xffffffffu, s, o);
    float scale = 1.0f / fmaxf(sqrtf(s), 1e-12f);

    float4* dst = reinterpret_cast<float4*>(g_Xn + (size_t)row * D);
    __nv_bfloat162* db = reinterpret_cast<__nv_bfloat162*>(g_Xb + (size_t)row * D);
#pragma unroll
    for (int i = 0; i < 4; i++) {
        v[i].x *= scale; v[i].y *= scale; v[i].z *= scale; v[i].w *= scale;
        dst[i * 32 + lane] = v[i];
        db[i * 64 + lane * 2 + 0] = __nv_bfloat162(__float2bfloat16(v[i].x), __float2bfloat16(v[i].y));
        db[i * 64 + lane * 2 + 1] = __nv_bfloat162(__float2bfloat16(v[i].z), __float2bfloat16(v[i].w));
    }
}

// ===========================================================================
// Kernel 2: bf16 HMMA GEMM + register top-6/lane + overlapped zero-fill.
// 128 CTAs = 64 M-tiles x 2 N-halves, 256 threads (8 warps; warp = 32x64).
// ===========================================================================
__global__ __launch_bounds__(TPB, 1) void fused_mma(float* __restrict__ out) {
    extern __shared__ char smem[];
    const uint32_t sb = smem_u32(smem);

    const int tid = threadIdx.x, wid = tid >> 5, lane = tid & 31;
    const int mtile = blockIdx.x >> 1, half = blockIdx.x & 1;
    const int rowBase = mtile * TILE_M, colHalf = half * 4096;
    const int wr = wid >> 1, wc = wid & 1;     // warp 32-row band, 64-col band

    // ---- resident A tile: 128 x 512 bf16, swizzled, 8 chunks of [128][64] ----
#pragma unroll
    for (int i = 0; i < 32; i++) {
        int lin = tid + i * TPB;
        int r = lin >> 6, seg = lin & 63;
        uint4 v = *reinterpret_cast<const uint4*>(&g_Xb[(size_t)(rowBase + r) * D + seg * 8]);
        uint32_t off = (uint32_t)((seg >> 3) * 16384 + r * 128 + (((seg & 7) ^ (r & 7)) << 4));
        *reinterpret_cast<uint4*>(smem + SM_A + off) = v;
    }

    // per-lane top-6 for each of this lane's 4 sim-rows (all indices static)
    float tv[4][TK]; int ti[4][TK];
#pragma unroll
    for (int rl = 0; rl < 4; rl++)
#pragma unroll
        for (int j = 0; j < TK; j++) { tv[rl][j] = -1e30f; ti[rl][j] = 0; }

    // ldmatrix lane -> (row, k8) mapping
    const int grp = lane >> 3, l7 = lane & 7;
    const int a_r  = ((grp & 1) << 3) | l7;
    const int a_k8 = grp >> 1;
    const int b_n  = ((grp >> 1) << 3) | l7;
    const int b_k8 = grp & 1;

    // cp.async per-thread B-slice addressing: thread covers 4 (r,seg) pairs
    const int cpr0 = tid >> 3, cpseg = tid & 7;   // + i*32 rows
    __syncthreads();   // A tile visible

    for (int t = 0; t < NTILES; t++) {
        const int colBase = colHalf + t * TILE_N;

        // ---- zero-fill 64 KB of this CTA's output region (fire & forget) ----
        {
            const float4 z = make_float4(0.f, 0.f, 0.f, 0.f);
#pragma unroll
            for (int i = 0; i < 16; i++) {
                int gi = t * 4096 + tid + i * 256;
                int r = gi >> 10, c = gi & 1023;
                *reinterpret_cast<float4*>(out + (size_t)(rowBase + r) * N + colHalf + c * 4) = z;
            }
        }

        // ---- prefetch B chunk 0 ----
#pragma unroll
        for (int i = 0; i < 4; i++) {
            int r = cpr0 + i * 32;
            CP16(sb + SM_B0 + r * 128 + ((cpseg ^ (r & 7)) << 4),
                 &g_Xb[(size_t)(colBase + r) * D + cpseg * 8]);
        }
        CP_COMMIT();

        float acc[2][8][4];
#pragma unroll
        for (int mf = 0; mf < 2; mf++)
#pragma unroll
            for (int nf = 0; nf < 8; nf++)
#pragma unroll
                for (int ri = 0; ri < 4; ri++) acc[mf][nf][ri] = 0.0f;

        for (int kc = 0; kc < 8; kc++) {
            CP_WAIT0();
            __syncthreads();   // chunk kc visible to all; buf (kc+1)&1 free

            if (kc < 7) {
                const uint32_t dstb = sb + (((kc + 1) & 1) ? SM_B1 : SM_B0);
#pragma unroll
                for (int i = 0; i < 4; i++) {
                    int r = cpr0 + i * 32;
                    CP16(dstb + r * 128 + ((cpseg ^ (r & 7)) << 4),
                         &g_Xb[(size_t)(colBase + r) * D + (kc + 1) * 64 + cpseg * 8]);
                }
                CP_COMMIT();
            }

            const uint32_t abase = sb + SM_A + kc * 16384;
            const uint32_t bbase = sb + ((kc & 1) ? SM_B1 : SM_B0);

#pragma unroll
            for (int ks = 0; ks < 4; ks++) {
                const int kb8 = ks * 2;
                uint32_t a0[4], a1[4];
                {
                    int r0 = wr * 32 + a_r;
                    ldsm4(a0, abase + r0 * 128 + (((kb8 + a_k8) ^ (r0 & 7)) << 4));
                    int r1 = r0 + 16;
                    ldsm4(a1, abase + r1 * 128 + (((kb8 + a_k8) ^ (r1 & 7)) << 4));
                }
                uint32_t bfr[4][4];
#pragma unroll
                for (int q = 0; q < 4; q++) {
                    int n = wc * 64 + q * 16 + b_n;
                    ldsm4(bfr[q], bbase + n * 128 + (((kb8 + b_k8) ^ (n & 7)) << 4));
                }
#pragma unroll
                for (int nf = 0; nf < 8; nf++) {
                    mma16816(acc[0][nf], a0, &bfr[nf >> 1][(nf & 1) * 2]);
                    mma16816(acc[1][nf], a1, &bfr[nf >> 1][(nf & 1) * 2]);
                }
            }
        }

        // ---- register top-k update: pure ALU, no syncs ----
        const int cbase = colBase + wc * 64 + ((lane & 3) << 1);
#pragma unroll
        for (int mf = 0; mf < 2; mf++)
#pragma unroll
            for (int nf = 0; nf < 8; nf++)
#pragma unroll
                for (int ri = 0; ri < 4; ri++) {
                    float v = acc[mf][nf][ri];
                    const int rl = mf * 2 + (ri >> 1);   // static
                    if (v > tv[rl][TK - 1]) {
                        int idx = cbase + nf * 8 + (ri & 1);
                        tv[rl][TK - 1] = v; ti[rl][TK - 1] = idx;
#pragma unroll
                        for (int p = TK - 1; p > 0; p--) {
                            if (tv[rl][p] > tv[rl][p - 1]) {
                                float fv = tv[rl][p]; tv[rl][p] = tv[rl][p - 1]; tv[rl][p - 1] = fv;
                                int   fi = ti[rl][p]; ti[rl][p] = ti[rl][p - 1]; ti[rl][p - 1] = fi;
                            }
                        }
                    }
                }
    }

    // ---- final merge: 48 candidates/row -> top-8 (reuse A smem region) ----
    __syncthreads();                       // everyone done reading A
    float* mval = reinterpret_cast<float*>(smem + SM_A);            // [128][48]
    int*   midx = reinterpret_cast<int*>(smem + SM_A + 24576);      // [128][48]
#pragma unroll
    for (int mf = 0; mf < 2; mf++)
#pragma unroll
        for (int b = 0; b < 2; b++) {
            int r = wr * 32 + mf * 16 + (lane >> 2) + 8 * b;
            int s0 = wc * 24 + (lane & 3) * 6;
            const int rl = mf * 2 + b;
#pragma unroll
            for (int j = 0; j < TK; j++) {
                mval[r * 48 + s0 + j] = tv[rl][j];
                midx[r * 48 + s0 + j] = ti[rl][j];
            }
        }
    __syncthreads();

    if (tid < 128) {
        float* rv = mval + tid * 48;
        int*   rixp = midx + tid * 48;
        int row = rowBase + tid;
#pragma unroll
        for (int sel = 0; sel < 8; sel++) {
            float bv = -1e30f; int bi = 0x7fffffff, bs = 0;
            for (int q = 0; q < 48; q++) {
                float v = rv[q]; int ix = rixp[q];
                if (v > bv || (v == bv && ix < bi)) { bv = v; bi = ix; bs = q; }
            }
            rv[bs] = -1e30f;
            g_cand_idx[row * 16 + half * 8 + sel] = bi;
        }
    }
}

// ===========================================================================
// Kernel 3: exact fp32 rescore of 16 candidates/row, top-5 (jax tie rule),
// softmax, scatter.  One warp per row.
// ===========================================================================
__global__ __launch_bounds__(256) void rescore_kernel(float* __restrict__ out) {
    const int wid = threadIdx.x >> 5, lane = threadIdx.x & 31;
    const int row = blockIdx.x * 8 + wid;

    float xr[16];
#pragma unroll
    for (int i = 0; i < 16; i++) xr[i] = g_Xn[(size_t)row * D + i * 32 + lane];

    float myv = -1e30f; int myi = 0x7fffffff;
#pragma unroll
    for (int c = 0; c < 16; c++) {
        int idx = g_cand_idx[row * 16 + c];
        const float* Xc = g_Xn + (size_t)idx * D;
        float s = 0.f;
#pragma unroll
        for (int i = 0; i < 16; i++) s = fmaf(xr[i], Xc[i * 32 + lane], s);
#pragma unroll
        for (int o = 16; o; o >>= 1) s += __shfl_xor_sync(0xffffffffu, s, o);
        if (lane == c) { myv = s; myi = idx; }
    }

    float sv[5]; int si[5];
#pragma unroll
    for (int r5 = 0; r5 < 5; r5++) {
        float v = myv; int i = myi;
#pragma unroll
        for (int o = 16; o; o >>= 1) {
            float ov = __shfl_xor_sync(0xffffffffu, v, o);
            int   oi = __shfl_xor_sync(0xffffffffu, i, o);
            if (ov > v || (ov == v && oi < i)) { v = ov; i = oi; }
        }
        sv[r5] = v; si[r5] = i;
        if (myi == i) { myv = -1e30f; myi = 0x7fffffff; }
    }

    if (lane == 0) {
        float m = sv[0];
        float e0 = expf((sv[0] - m) * TEMP_INV);
        float e1 = expf((sv[1] - m) * TEMP_INV);
        float e2 = expf((sv[2] - m) * TEMP_INV);
        float e3 = expf((sv[3] - m) * TEMP_INV);
        float e4 = expf((sv[4] - m) * TEMP_INV);
        float inv = 1.0f / (e0 + e1 + e2 + e3 + e4);
        float* o = out + (size_t)row * N;
        o[si[0]] = e0 * inv; o[si[1]] = e1 * inv; o[si[2]] = e2 * inv;
        o[si[3]] = e3 * inv; o[si[4]] = e4 * inv;
    }
}

// ===========================================================================
extern "C" void kernel_launch(void* const* d_in, const int* in_sizes, int n_in,
                              void* d_out, int out_size) {
    (void)in_sizes; (void)n_in; (void)out_size;
    const float* X   = (const float*)d_in[0];
    float*       out = (float*)d_out;

    cudaFuncSetAttribute(fused_mma, cudaFuncAttributeMaxDynamicSharedMemorySize, SMEM_TOTAL);

    normalize_kernel<<<N / 8, 256>>>(X);
    fused_mma<<<128, TPB, SMEM_TOTAL>>>(out);
    rescore_kernel<<<N / 8, 256>>>(out);
}

// round 5
// speedup vs baseline: 6.0780x; 1.0060x over previous
#include <cuda_runtime.h>
#include <cuda_bf16.h>
#include <cstdint>
#include <math.h>

#define N 8192
#define D 512
#define TEMP_INV 10.0f

#define TILE_M 128
#define TILE_N 128
#define NTILES 32          // column tiles per CTA (4096/128)
#define TPB    256
#define TK     6           // per-lane top-K per row

// ---- device scratch (static; no allocations allowed) ----
__device__ float    g_Xn[N * D];     // 16 MB fp32 normalized (exact rescore)
__device__ uint8_t  g_X8[N * D];     // 4 MB e4m3 normalized*16 (GEMM)
__device__ int      g_cand_idx[N * 16];

// ---- SMEM layout ----
// A: 4 chunks x [128 rows][128B k] e4m3, swizzled = 64KB (reused for merge)
// B: two cp.async buffers [128][128B] = 16KB each
#define SM_A   0
#define SM_B0  65536
#define SM_B1  81920
#define SMEM_TOTAL 98304    // 96 KB

// ================= helpers =================
__device__ __forceinline__ uint32_t smem_u32(const void* p) {
    uint32_t a;
    asm("{ .reg .u64 t; cvta.to.shared.u64 t, %1; cvt.u32.u64 %0, t; }" : "=r"(a) : "l"(p));
    return a;
}
__device__ __forceinline__ void ldsm4(uint32_t* r, uint32_t addr) {
    asm volatile("ldmatrix.sync.aligned.m8n8.x4.shared.b16 {%0,%1,%2,%3}, [%4];"
                 : "=r"(r[0]), "=r"(r[1]), "=r"(r[2]), "=r"(r[3]) : "r"(addr));
}
// fp8 e4m3 MMA, fp32 accum: m16n8k32. Fragment layout == bf16 k16 with
// "b16 element" = 2 consecutive fp8 -> identical ldmatrix addressing.
__device__ __forceinline__ void mma_fp8(float* c, const uint32_t* a, const uint32_t* b) {
    asm volatile("mma.sync.aligned.m16n8k32.row.col.f32.e4m3.e4m3.f32 "
                 "{%0,%1,%2,%3}, {%4,%5,%6,%7}, {%8,%9}, {%0,%1,%2,%3};"
                 : "+f"(c[0]), "+f"(c[1]), "+f"(c[2]), "+f"(c[3])
                 : "r"(a[0]), "r"(a[1]), "r"(a[2]), "r"(a[3]), "r"(b[0]), "r"(b[1]));
}
__device__ __forceinline__ uint32_t pack4_e4m3(float x, float y, float z, float w) {
    uint16_t lo, hi;   // cvt packs 2nd src into low byte
    asm("cvt.rn.satfinite.e4m3x2.f32 %0, %1, %2;" : "=h"(lo) : "f"(y), "f"(x));
    asm("cvt.rn.satfinite.e4m3x2.f32 %0, %1, %2;" : "=h"(hi) : "f"(w), "f"(z));
    return (uint32_t)lo | ((uint32_t)hi << 16);
}
#define CP16(sa, gp) \
    asm volatile("cp.async.cg.shared.global [%0], [%1], 16;" :: "r"(sa), "l"(gp) : "memory")
#define CP_COMMIT()  asm volatile("cp.async.commit_group;" ::: "memory")
#define CP_WAIT0()   asm volatile("cp.async.wait_group 0;" ::: "memory")

// ===========================================================================
// Kernel 1: L2-normalize rows -> fp32 + e4m3(x16).  One warp per row.
// ===========================================================================
__global__ void normalize_kernel(const float* __restrict__ X) {
    int row  = blockIdx.x * 8 + (threadIdx.x >> 5);
    int lane = threadIdx.x & 31;
    const float4* src = reinterpret_cast<const float4*>(X + (size_t)row * D);

    float4 v[4];
    float s = 0.0f;
#pragma unroll
    for (int i = 0; i < 4; i++) {
        v[i] = src[i * 32 + lane];
        s += v[i].x*v[i].x + v[i].y*v[i].y + v[i].z*v[i].z + v[i].w*v[i].w;
    }
#pragma unroll
    for (int o = 16; o; o >>= 1) s += __shfl_xor_sync(0xffffffffu, s, o);
    float scale = 1.0f / fmaxf(sqrtf(s), 1e-12f);

    float4* dst = reinterpret_cast<float4*>(g_Xn + (size_t)row * D);
    uint32_t* d8 = reinterpret_cast<uint32_t*>(g_X8 + (size_t)row * D);
#pragma unroll
    for (int i = 0; i < 4; i++) {
        v[i].x *= scale; v[i].y *= scale; v[i].z *= scale; v[i].w *= scale;
        dst[i * 32 + lane] = v[i];
        // scale *16 into e4m3 sweet spot (monotone; only ranking matters)
        d8[i * 32 + lane] = pack4_e4m3(16.f * v[i].x, 16.f * v[i].y,
                                       16.f * v[i].z, 16.f * v[i].w);
    }
}

// ===========================================================================
// Kernel 2: e4m3 HMMA GEMM (fp32 accum) + register top-6/lane + zero-fill.
// 128 CTAs = 64 M-tiles x 2 N-halves, 256 threads (8 warps; warp = 32x64).
// ===========================================================================
__global__ __launch_bounds__(TPB, 1) void fused_mma(float* __restrict__ out) {
    extern __shared__ char smem[];
    const uint32_t sb = smem_u32(smem);

    const int tid = threadIdx.x, wid = tid >> 5, lane = tid & 31;
    const int mtile = blockIdx.x >> 1, half = blockIdx.x & 1;
    const int rowBase = mtile * TILE_M, colHalf = half * 4096;
    const int wr = wid >> 1, wc = wid & 1;     // warp 32-row band, 64-col band

    // ---- resident A tile: 128 x 512 e4m3, 4 swizzled chunks of [128][128B] ----
#pragma unroll
    for (int i = 0; i < 16; i++) {
        int lin = tid + i * TPB;
        int r = lin >> 5, s = lin & 31;                 // s = 16B slot in row
        uint4 v = *reinterpret_cast<const uint4*>(&g_X8[(size_t)(rowBase + r) * D + s * 16]);
        int chunk = s >> 3, seg = s & 7;
        *reinterpret_cast<uint4*>(smem + SM_A + chunk * 16384 + r * 128 +
                                  (((seg ^ (r & 7)) << 4))) = v;
    }

    // per-lane top-6 for each of this lane's 4 sim-rows
    float tv[4][TK]; int ti[4][TK];
#pragma unroll
    for (int rl = 0; rl < 4; rl++)
#pragma unroll
        for (int j = 0; j < TK; j++) { tv[rl][j] = -1e30f; ti[rl][j] = 0; }

    // ldmatrix lane -> (row, seg) mapping (16B seg = 16 fp8 = k16)
    const int grp = lane >> 3, l7 = lane & 7;
    const int a_r  = ((grp & 1) << 3) | l7;
    const int a_s  = grp >> 1;
    const int b_n  = ((grp >> 1) << 3) | l7;
    const int b_s  = grp & 1;

    // cp.async per-thread B-slice: 4 of 1024 16B slots
    const int cpr0 = tid >> 3, cpseg = tid & 7;        // + i*32 rows
    __syncthreads();   // A tile visible

    for (int t = 0; t < NTILES; t++) {
        const int colBase = colHalf + t * TILE_N;

        // ---- zero-fill 64 KB of this CTA's output region (fire & forget) ----
        {
            const float4 z = make_float4(0.f, 0.f, 0.f, 0.f);
#pragma unroll
            for (int i = 0; i < 16; i++) {
                int gi = t * 4096 + tid + i * 256;
                int r = gi >> 10, c = gi & 1023;
                *reinterpret_cast<float4*>(out + (size_t)(rowBase + r) * N + colHalf + c * 4) = z;
            }
        }

        // ---- prefetch B chunk 0 ----
#pragma unroll
        for (int i = 0; i < 4; i++) {
            int r = cpr0 + i * 32;
            CP16(sb + SM_B0 + r * 128 + ((cpseg ^ (r & 7)) << 4),
                 &g_X8[(size_t)(colBase + r) * D + cpseg * 16]);
        }
        CP_COMMIT();

        float acc[2][8][4];
#pragma unroll
        for (int mf = 0; mf < 2; mf++)
#pragma unroll
            for (int nf = 0; nf < 8; nf++)
#pragma unroll
                for (int ri = 0; ri < 4; ri++) acc[mf][nf][ri] = 0.0f;

        for (int kc = 0; kc < 4; kc++) {
            CP_WAIT0();
            __syncthreads();   // chunk kc visible; other buffer free

            if (kc < 3) {
                const uint32_t dstb = sb + (((kc + 1) & 1) ? SM_B1 : SM_B0);
#pragma unroll
                for (int i = 0; i < 4; i++) {
                    int r = cpr0 + i * 32;
                    CP16(dstb + r * 128 + ((cpseg ^ (r & 7)) << 4),
                         &g_X8[(size_t)(colBase + r) * D + (kc + 1) * 128 + cpseg * 16]);
                }
                CP_COMMIT();
            }

            const uint32_t abase = sb + SM_A + kc * 16384;
            const uint32_t bbase = sb + ((kc & 1) ? SM_B1 : SM_B0);

#pragma unroll
            for (int ks = 0; ks < 4; ks++) {           // 4 x k32 per 128-fp8 chunk
                const int sg = ks * 2;
                uint32_t a0[4], a1[4];
                {
                    int r0 = wr * 32 + a_r;
                    ldsm4(a0, abase + r0 * 128 + (((sg + a_s) ^ (r0 & 7)) << 4));
                    int r1 = r0 + 16;
                    ldsm4(a1, abase + r1 * 128 + (((sg + a_s) ^ (r1 & 7)) << 4));
                }
                uint32_t bfr[4][4];
#pragma unroll
                for (int q = 0; q < 4; q++) {
                    int n = wc * 64 + q * 16 + b_n;
                    ldsm4(bfr[q], bbase + n * 128 + (((sg + b_s) ^ (n & 7)) << 4));
                }
#pragma unroll
                for (int nf = 0; nf < 8; nf++) {
                    mma_fp8(acc[0][nf], a0, &bfr[nf >> 1][(nf & 1) * 2]);
                    mma_fp8(acc[1][nf], a1, &bfr[nf >> 1][(nf & 1) * 2]);
                }
            }
        }

        // ---- register top-k update: pure ALU, no syncs ----
        const int cbase = colBase + wc * 64 + ((lane & 3) << 1);
#pragma unroll
        for (int mf = 0; mf < 2; mf++)
#pragma unroll
            for (int nf = 0; nf < 8; nf++)
#pragma unroll
                for (int ri = 0; ri < 4; ri++) {
                    float v = acc[mf][nf][ri];
                    const int rl = mf * 2 + (ri >> 1);
                    if (v > tv[rl][TK - 1]) {
                        int idx = cbase + nf * 8 + (ri & 1);
                        tv[rl][TK - 1] = v; ti[rl][TK - 1] = idx;
#pragma unroll
                        for (int p = TK - 1; p > 0; p--) {
                            if (tv[rl][p] > tv[rl][p - 1]) {
                                float fv = tv[rl][p]; tv[rl][p] = tv[rl][p - 1]; tv[rl][p - 1] = fv;
                                int   fi = ti[rl][p]; ti[rl][p] = ti[rl][p - 1]; ti[rl][p - 1] = fi;
                            }
                        }
                    }
                }
    }

    // ---- final merge: 48 candidates/row -> top-8 (reuse A smem region) ----
    __syncthreads();
    float* mval = reinterpret_cast<float*>(smem + SM_A);            // [128][48]
    int*   midx = reinterpret_cast<int*>(smem + SM_A + 24576);      // [128][48]
#pragma unroll
    for (int mf = 0; mf < 2; mf++)
#pragma unroll
        for (int b = 0; b < 2; b++) {
            int r = wr * 32 + mf * 16 + (lane >> 2) + 8 * b;
            int s0 = wc * 24 + (lane & 3) * 6;
            const int rl = mf * 2 + b;
#pragma unroll
            for (int j = 0; j < TK; j++) {
                mval[r * 48 + s0 + j] = tv[rl][j];
                midx[r * 48 + s0 + j] = ti[rl][j];
            }
        }
    __syncthreads();

    if (tid < 128) {
        float* rv = mval + tid * 48;
        int*   rixp = midx + tid * 48;
        int row = rowBase + tid;
#pragma unroll
        for (int sel = 0; sel < 8; sel++) {
            float bv = -1e30f; int bi = 0x7fffffff, bs = 0;
            for (int q = 0; q < 48; q++) {
                float v = rv[q]; int ix = rixp[q];
                if (v > bv || (v == bv && ix < bi)) { bv = v; bi = ix; bs = q; }
            }
            rv[bs] = -1e30f;
            g_cand_idx[row * 16 + half * 8 + sel] = bi;
        }
    }
}

// ===========================================================================
// Kernel 3: exact fp32 rescore of 16 candidates/row, top-5 (jax tie rule),
// softmax, scatter.  One warp per row.
// ===========================================================================
__global__ __launch_bounds__(256) void rescore_kernel(float* __restrict__ out) {
    const int wid = threadIdx.x >> 5, lane = threadIdx.x & 31;
    const int row = blockIdx.x * 8 + wid;

    float xr[16];
#pragma unroll
    for (int i = 0; i < 16; i++) xr[i] = g_Xn[(size_t)row * D + i * 32 + lane];

    float myv = -1e30f; int myi = 0x7fffffff;
#pragma unroll
    for (int c = 0; c < 16; c++) {
        int idx = g_cand_idx[row * 16 + c];
        const float* Xc = g_Xn + (size_t)idx * D;
        float s = 0.f;
#pragma unroll
        for (int i = 0; i < 16; i++) s = fmaf(xr[i], Xc[i * 32 + lane], s);
#pragma unroll
        for (int o = 16; o; o >>= 1) s += __shfl_xor_sync(0xffffffffu, s, o);
        if (lane == c) { myv = s; myi = idx; }
    }

    float sv[5]; int si[5];
#pragma unroll
    for (int r5 = 0; r5 < 5; r5++) {
        float v = myv; int i = myi;
#pragma unroll
        for (int o = 16; o; o >>= 1) {
            float ov = __shfl_xor_sync(0xffffffffu, v, o);
            int   oi = __shfl_xor_sync(0xffffffffu, i, o);
            if (ov > v || (ov == v && oi < i)) { v = ov; i = oi; }
        }
        sv[r5] = v; si[r5] = i;
        if (myi == i) { myv = -1e30f; myi = 0x7fffffff; }
    }

    if (lane == 0) {
        float m = sv[0];
        float e0 = expf((sv[0] - m) * TEMP_INV);
        float e1 = expf((sv[1] - m) * TEMP_INV);
        float e2 = expf((sv[2] - m) * TEMP_INV);
        float e3 = expf((sv[3] - m) * TEMP_INV);
        float e4 = expf((sv[4] - m) * TEMP_INV);
        float inv = 1.0f / (e0 + e1 + e2 + e3 + e4);
        float* o = out + (size_t)row * N;
        o[si[0]] = e0 * inv; o[si[1]] = e1 * inv; o[si[2]] = e2 * inv;
        o[si[3]] = e3 * inv; o[si[4]] = e4 * inv;
    }
}

// ===========================================================================
extern "C" void kernel_launch(void* const* d_in, const int* in_sizes, int n_in,
                              void* d_out, int out_size) {
    (void)in_sizes; (void)n_in; (void)out_size;
    const float* X   = (const float*)d_in[0];
    float*       out = (float*)d_out;

    cudaFuncSetAttribute(fused_mma, cudaFuncAttributeMaxDynamicSharedMemorySize, SMEM_TOTAL);

    normalize_kernel<<<N / 8, 256>>>(X);
    fused_mma<<<128, TPB, SMEM_TOTAL>>>(out);
    rescore_kernel<<<N / 8, 256>>>(out);
}

// round 6
// speedup vs baseline: 6.5049x; 1.0702x over previous
#include <cuda_runtime.h>
#include <cuda_bf16.h>
#include <cstdint>
#include <math.h>

#define N 8192
#define D 512
#define TEMP_INV 10.0f

#define NB    64          // 128-row bands
#define NTT   2080        // NB*(NB+1)/2 upper-triangle tiles
#define G     148         // CTAs (one wave)
#define TPB   256
#define RT    8           // per-segment top-K kept
#define SEL   12          // candidates rescored exactly

// ---- device scratch (static; no allocations allowed) ----
__device__ float    g_Xn[N * D];        // 16 MB fp32 normalized (exact rescore)
__device__ uint8_t  g_X8[N * D];        // 4 MB e4m3 normalized*16 (GEMM)
__device__ float2   g_cand[N * 64 * 8]; // 32 MB candidate table (val, idx)

// ---- SMEM: A band 64KB | B band 64KB | C tile 64KB ----
#define SM_A   0
#define SM_B   65536
#define SM_C   131072
#define SMEM_TOTAL 196608   // 192 KB

// ================= helpers =================
__device__ __forceinline__ uint32_t smem_u32(const void* p) {
    uint32_t a;
    asm("{ .reg .u64 t; cvta.to.shared.u64 t, %1; cvt.u32.u64 %0, t; }" : "=r"(a) : "l"(p));
    return a;
}
__device__ __forceinline__ void ldsm4(uint32_t* r, uint32_t addr) {
    asm volatile("ldmatrix.sync.aligned.m8n8.x4.shared.b16 {%0,%1,%2,%3}, [%4];"
                 : "=r"(r[0]), "=r"(r[1]), "=r"(r[2]), "=r"(r[3]) : "r"(addr));
}
__device__ __forceinline__ void mma_fp8(float* c, const uint32_t* a, const uint32_t* b) {
    asm volatile("mma.sync.aligned.m16n8k32.row.col.f32.e4m3.e4m3.f32 "
                 "{%0,%1,%2,%3}, {%4,%5,%6,%7}, {%8,%9}, {%0,%1,%2,%3};"
                 : "+f"(c[0]), "+f"(c[1]), "+f"(c[2]), "+f"(c[3])
                 : "r"(a[0]), "r"(a[1]), "r"(a[2]), "r"(a[3]), "r"(b[0]), "r"(b[1]));
}
__device__ __forceinline__ uint32_t pack4_e4m3(float x, float y, float z, float w) {
    uint16_t lo, hi;
    asm("cvt.rn.satfinite.e4m3x2.f32 %0, %1, %2;" : "=h"(lo) : "f"(y), "f"(x));
    asm("cvt.rn.satfinite.e4m3x2.f32 %0, %1, %2;" : "=h"(hi) : "f"(w), "f"(z));
    return (uint32_t)lo | ((uint32_t)hi << 16);
}
#define CP16(sa, gp) \
    asm volatile("cp.async.cg.shared.global [%0], [%1], 16;" :: "r"(sa), "l"(gp) : "memory")
#define CP_COMMIT()  asm volatile("cp.async.commit_group;" ::: "memory")
#define CP_WAIT0()   asm volatile("cp.async.wait_group 0;" ::: "memory")

// load a 128-row fp8 band (64 KB) into swizzled smem (4 chunks x [128][128B])
__device__ __forceinline__ void load_band(uint32_t sbase, int band, int tid) {
#pragma unroll
    for (int ch = 0; ch < 4; ch++)
#pragma unroll
        for (int q = 0; q < 4; q++) {
            int lin = tid + q * TPB;            // 0..1023
            int r = lin >> 3, seg = lin & 7;
            CP16(sbase + ch * 16384 + r * 128 + ((seg ^ (r & 7)) << 4),
                 &g_X8[(size_t)(band * 128 + r) * D + ch * 128 + seg * 16]);
        }
}

// ===========================================================================
// Kernel 1: L2-normalize rows -> fp32 + e4m3(x16).  One warp per row.
// ===========================================================================
__global__ void normalize_kernel(const float* __restrict__ X) {
    int row  = blockIdx.x * 8 + (threadIdx.x >> 5);
    int lane = threadIdx.x & 31;
    const float4* src = reinterpret_cast<const float4*>(X + (size_t)row * D);

    float4 v[4];
    float s = 0.0f;
#pragma unroll
    for (int i = 0; i < 4; i++) {
        v[i] = src[i * 32 + lane];
        s += v[i].x*v[i].x + v[i].y*v[i].y + v[i].z*v[i].z + v[i].w*v[i].w;
    }
#pragma unroll
    for (int o = 16; o; o >>= 1) s += __shfl_xor_sync(0xffffffffu, s, o);
    float scale = 1.0f / fmaxf(sqrtf(s), 1e-12f);

    float4* dst = reinterpret_cast<float4*>(g_Xn + (size_t)row * D);
    uint32_t* d8 = reinterpret_cast<uint32_t*>(g_X8 + (size_t)row * D);
#pragma unroll
    for (int i = 0; i < 4; i++) {
        v[i].x *= scale; v[i].y *= scale; v[i].z *= scale; v[i].w *= scale;
        dst[i * 32 + lane] = v[i];
        d8[i * 32 + lane] = pack4_e4m3(16.f * v[i].x, 16.f * v[i].y,
                                       16.f * v[i].z, 16.f * v[i].w);
    }
}

// ===========================================================================
// Kernel 2: symmetric-triangle fp8 GEMM; per tile emits row-scan AND col-scan
// top-8 candidates; zero-fills (i,j) and mirror (j,i) output blocks.
// ===========================================================================
__global__ __launch_bounds__(TPB, 1) void tile_kernel(float* __restrict__ out) {
    extern __shared__ char smem[];
    const uint32_t sb = smem_u32(smem);
    float* Cs = reinterpret_cast<float*>(smem + SM_C);

    const int tid = threadIdx.x, wid = tid >> 5, lane = tid & 31;
    const int wr = wid >> 1, wc = wid & 1;
    const int bid = blockIdx.x;

    // blocked uneven partition: first 8 CTAs get 15 tiles, rest 14
    const int start = bid * 14 + (bid < 8 ? bid : 8);
    const int cnt   = (bid < 8) ? 15 : 14;

    // ldmatrix lane mapping (16B seg = k16 fp8-pairs)
    const int grp = lane >> 3, l7 = lane & 7;
    const int a_r = ((grp & 1) << 3) | l7, a_s = grp >> 1;
    const int b_n = ((grp >> 1) << 3) | l7, b_s = grp & 1;

    // decode first tile
    int t0 = start, i, j;
    {
        int rem = t0, ii = 0;
        while (rem >= NB - ii) { rem -= NB - ii; ii++; }
        i = ii; j = ii + rem;
    }
    load_band(sb + SM_A, i, tid);
    load_band(sb + SM_B, j, tid);
    CP_COMMIT();
    int curA = i;

    for (int u = 0; u < cnt; u++) {
        CP_WAIT0();
        __syncthreads();           // A/B (and Cs free) ready

        // ---- zero-fill output blocks (i,j) and mirror ----
        {
            const float4 z = make_float4(0.f, 0.f, 0.f, 0.f);
#pragma unroll
            for (int q = 0; q < 16; q++) {
                int lin = tid + q * TPB;
                int r = lin >> 5, c4 = lin & 31;
                *reinterpret_cast<float4*>(out + (size_t)(i * 128 + r) * N + j * 128 + c4 * 4) = z;
            }
            if (i != j) {
#pragma unroll
                for (int q = 0; q < 16; q++) {
                    int lin = tid + q * TPB;
                    int r = lin >> 5, c4 = lin & 31;
                    *reinterpret_cast<float4*>(out + (size_t)(j * 128 + r) * N + i * 128 + c4 * 4) = z;
                }
            }
        }

        // ---- mainloop: 16 x k32 over full K=512 in smem ----
        float acc[2][8][4];
#pragma unroll
        for (int mf = 0; mf < 2; mf++)
#pragma unroll
            for (int nf = 0; nf < 8; nf++)
#pragma unroll
                for (int ri = 0; ri < 4; ri++) acc[mf][nf][ri] = 0.0f;

#pragma unroll
        for (int ks = 0; ks < 16; ks++) {
            const int ch = ks >> 2, sg = (ks & 3) * 2;
            const uint32_t abase = sb + SM_A + ch * 16384;
            const uint32_t bbase = sb + SM_B + ch * 16384;
            uint32_t a0[4], a1[4];
            {
                int r0 = wr * 32 + a_r;
                ldsm4(a0, abase + r0 * 128 + (((sg + a_s) ^ (r0 & 7)) << 4));
                int r1 = r0 + 16;
                ldsm4(a1, abase + r1 * 128 + (((sg + a_s) ^ (r1 & 7)) << 4));
            }
            uint32_t bfr[4][4];
#pragma unroll
            for (int q = 0; q < 4; q++) {
                int n = wc * 64 + q * 16 + b_n;
                ldsm4(bfr[q], bbase + n * 128 + (((sg + b_s) ^ (n & 7)) << 4));
            }
#pragma unroll
            for (int nf = 0; nf < 8; nf++) {
                mma_fp8(acc[0][nf], a0, &bfr[nf >> 1][(nf & 1) * 2]);
                mma_fp8(acc[1][nf], a1, &bfr[nf >> 1][(nf & 1) * 2]);
            }
        }
        __syncthreads();           // all A/B smem reads done

        // ---- prefetch next tile's bands (overlaps epilogue) ----
        int ni = i, nj = j;
        if (u + 1 < cnt) {
            int t = start + u + 1;
            int rem = t, ii = 0;
            while (rem >= NB - ii) { rem -= NB - ii; ii++; }
            ni = ii; nj = ii + rem;
            if (ni != curA) { load_band(sb + SM_A, ni, tid); curA = ni; }
            load_band(sb + SM_B, nj, tid);
            CP_COMMIT();
        }

        // ---- stage C to smem (col XOR row&31 swizzle) ----
#pragma unroll
        for (int mf = 0; mf < 2; mf++)
#pragma unroll
            for (int nf = 0; nf < 8; nf++)
#pragma unroll
                for (int ri = 0; ri < 4; ri++) {
                    int row = wr * 32 + mf * 16 + (lane >> 2) + ((ri >> 1) << 3);
                    int col = wc * 64 + nf * 8 + ((lane & 3) << 1) + (ri & 1);
                    Cs[row * 128 + (col ^ (row & 31))] = acc[mf][nf][ri];
                }
        __syncthreads();

        // ---- scans: threads 0-127 rows, threads 128-255 columns ----
        float tv[RT]; int ti[RT];
#pragma unroll
        for (int q = 0; q < RT; q++) { tv[q] = -1e30f; ti[q] = 0; }

        if (tid < 128) {
            const int r = tid, rx = r & 31;
            const float* crow = Cs + r * 128;
            for (int c = 0; c < 128; c++) {
                float v = crow[c ^ rx];
                if (v > tv[RT - 1]) {
                    tv[RT - 1] = v; ti[RT - 1] = j * 128 + c;
#pragma unroll
                    for (int p = RT - 1; p > 0; p--)
                        if (tv[p] > tv[p - 1]) {
                            float fv = tv[p]; tv[p] = tv[p - 1]; tv[p - 1] = fv;
                            int   fi = ti[p]; ti[p] = ti[p - 1]; ti[p - 1] = fi;
                        }
                }
            }
            float2* dst = &g_cand[((size_t)(i * 128 + r) * 64 + j) * 8];
#pragma unroll
            for (int q = 0; q < RT; q++)
                dst[q] = make_float2(tv[q], __int_as_float(ti[q]));
        } else if (i != j) {
            const int c = tid - 128;
            for (int r = 0; r < 128; r++) {
                float v = Cs[r * 128 + (c ^ (r & 31))];
                if (v > tv[RT - 1]) {
                    tv[RT - 1] = v; ti[RT - 1] = i * 128 + r;
#pragma unroll
                    for (int p = RT - 1; p > 0; p--)
                        if (tv[p] > tv[p - 1]) {
                            float fv = tv[p]; tv[p] = tv[p - 1]; tv[p - 1] = fv;
                            int   fi = ti[p]; ti[p] = ti[p - 1]; ti[p - 1] = fi;
                        }
                }
            }
            float2* dst = &g_cand[((size_t)(j * 128 + c) * 64 + i) * 8];
#pragma unroll
            for (int q = 0; q < RT; q++)
                dst[q] = make_float2(tv[q], __int_as_float(ti[q]));
        }
        i = ni; j = nj;
        // next iteration's CP_WAIT0 + __syncthreads protects Cs/A/B reuse
    }
}

// ===========================================================================
// Kernel 3: per-row merge of 64 sorted 8-lists -> top-12 (fp8 values), exact
// fp32 rescore, top-5 (jax tie rule), softmax, scatter.  One warp per row.
// ===========================================================================
__global__ __launch_bounds__(256) void merge_rescore(float* __restrict__ out) {
    const int wid = threadIdx.x >> 5, lane = threadIdx.x & 31;
    const int row = blockIdx.x * 8 + wid;

    const float2* base = g_cand + (size_t)row * 512;
    // lane owns sorted slot lists  lane  and  lane+32
    int h0 = 0, h1 = 0;
    float2 e;
    e = base[lane * 8];        float cv0 = e.x; int ci0 = __float_as_int(e.y);
    e = base[(lane + 32) * 8]; float cv1 = e.x; int ci1 = __float_as_int(e.y);

    int selidx[SEL];
#pragma unroll
    for (int it = 0; it < SEL; it++) {
        bool p0 = (cv0 > cv1) || (cv0 == cv1 && ci0 <= ci1);
        float v = p0 ? cv0 : cv1;
        int  ix = p0 ? ci0 : ci1;
        float bv = v; int bi = ix, bl = lane;
#pragma unroll
        for (int o = 16; o; o >>= 1) {
            float ov = __shfl_xor_sync(0xffffffffu, bv, o);
            int   oi = __shfl_xor_sync(0xffffffffu, bi, o);
            int   ol = __shfl_xor_sync(0xffffffffu, bl, o);
            if (ov > bv || (ov == bv && oi < bi)) { bv = ov; bi = oi; bl = ol; }
        }
        selidx[it] = bi;
        if (bl == lane) {
            if (p0) {
                h0++;
                if (h0 < 8) { e = base[lane * 8 + h0]; cv0 = e.x; ci0 = __float_as_int(e.y); }
                else cv0 = -1e30f;
            } else {
                h1++;
                if (h1 < 8) { e = base[(lane + 32) * 8 + h1]; cv1 = e.x; ci1 = __float_as_int(e.y); }
                else cv1 = -1e30f;
            }
        }
    }

    // ---- exact fp32 rescore of the 12 selected ----
    float xr[16];
#pragma unroll
    for (int q = 0; q < 16; q++) xr[q] = g_Xn[(size_t)row * D + q * 32 + lane];

    float myv = -1e30f; int myi = 0x7fffffff;
#pragma unroll
    for (int c = 0; c < SEL; c++) {
        int idx = selidx[c];
        const float* Xc = g_Xn + (size_t)idx * D;
        float s = 0.f;
#pragma unroll
        for (int q = 0; q < 16; q++) s = fmaf(xr[q], Xc[q * 32 + lane], s);
#pragma unroll
        for (int o = 16; o; o >>= 1) s += __shfl_xor_sync(0xffffffffu, s, o);
        if (lane == c) { myv = s; myi = idx; }
    }

    float sv[5]; int si[5];
#pragma unroll
    for (int r5 = 0; r5 < 5; r5++) {
        float v = myv; int ix = myi;
#pragma unroll
        for (int o = 16; o; o >>= 1) {
            float ov = __shfl_xor_sync(0xffffffffu, v, o);
            int   oi = __shfl_xor_sync(0xffffffffu, ix, o);
            if (ov > v || (ov == v && oi < ix)) { v = ov; ix = oi; }
        }
        sv[r5] = v; si[r5] = ix;
        if (myi == ix) { myv = -1e30f; myi = 0x7fffffff; }
    }

    if (lane == 0) {
        float m = sv[0];
        float e0 = expf((sv[0] - m) * TEMP_INV);
        float e1 = expf((sv[1] - m) * TEMP_INV);
        float e2 = expf((sv[2] - m) * TEMP_INV);
        float e3 = expf((sv[3] - m) * TEMP_INV);
        float e4 = expf((sv[4] - m) * TEMP_INV);
        float inv = 1.0f / (e0 + e1 + e2 + e3 + e4);
        float* o = out + (size_t)row * N;
        o[si[0]] = e0 * inv; o[si[1]] = e1 * inv; o[si[2]] = e2 * inv;
        o[si[3]] = e3 * inv; o[si[4]] = e4 * inv;
    }
}

// ===========================================================================
extern "C" void kernel_launch(void* const* d_in, const int* in_sizes, int n_in,
                              void* d_out, int out_size) {
    (void)in_sizes; (void)n_in; (void)out_size;
    const float* X   = (const float*)d_in[0];
    float*       out = (float*)d_out;

    cudaFuncSetAttribute(tile_kernel, cudaFuncAttributeMaxDynamicSharedMemorySize, SMEM_TOTAL);

    normalize_kernel<<<N / 8, 256>>>(X);
    tile_kernel<<<G, TPB, SMEM_TOTAL>>>(out);
    merge_rescore<<<N / 8, 256>>>(out);
}

// round 7
// speedup vs baseline: 8.0448x; 1.2367x over previous
#include <cuda_runtime.h>
#include <cuda_bf16.h>
#include <cstdint>
#include <math.h>

#define N 8192
#define D 512
#define TEMP_INV 10.0f

#define NB    64          // 128-row bands
#define NTT   2080        // NB*(NB+1)/2 upper-triangle tiles
#define G2    296         // CTAs (2 per SM, one wave)
#define TPB   256
#define RT    8           // per-slot top-K kept
#define SEL   12          // candidates rescored exactly

// ---- device scratch (static; no allocations allowed) ----
__device__ float    g_Xn[N * D];        // 16 MB fp32 normalized (exact rescore)
__device__ uint8_t  g_X8[N * D];        // 4 MB e4m3 normalized*16 (GEMM)
__device__ float2   g_cand[N * 64 * 8]; // 33.5 MB candidate table (val, idx)

// ---- SMEM: A dbl 2x16K | B dbl 2x16K | C bf16 32K  = 96 KB ----
#define SM_A0  0
#define SM_A1  16384
#define SM_B0  32768
#define SM_B1  49152
#define SM_C   65536
#define SMEM_TOTAL 98304

// ================= helpers =================
__device__ __forceinline__ uint32_t smem_u32(const void* p) {
    uint32_t a;
    asm("{ .reg .u64 t; cvta.to.shared.u64 t, %1; cvt.u32.u64 %0, t; }" : "=r"(a) : "l"(p));
    return a;
}
__device__ __forceinline__ void ldsm4(uint32_t* r, uint32_t addr) {
    asm volatile("ldmatrix.sync.aligned.m8n8.x4.shared.b16 {%0,%1,%2,%3}, [%4];"
                 : "=r"(r[0]), "=r"(r[1]), "=r"(r[2]), "=r"(r[3]) : "r"(addr));
}
__device__ __forceinline__ void mma_fp8(float* c, const uint32_t* a, const uint32_t* b) {
    asm volatile("mma.sync.aligned.m16n8k32.row.col.f32.e4m3.e4m3.f32 "
                 "{%0,%1,%2,%3}, {%4,%5,%6,%7}, {%8,%9}, {%0,%1,%2,%3};"
                 : "+f"(c[0]), "+f"(c[1]), "+f"(c[2]), "+f"(c[3])
                 : "r"(a[0]), "r"(a[1]), "r"(a[2]), "r"(a[3]), "r"(b[0]), "r"(b[1]));
}
__device__ __forceinline__ uint32_t pack4_e4m3(float x, float y, float z, float w) {
    uint16_t lo, hi;
    asm("cvt.rn.satfinite.e4m3x2.f32 %0, %1, %2;" : "=h"(lo) : "f"(y), "f"(x));
    asm("cvt.rn.satfinite.e4m3x2.f32 %0, %1, %2;" : "=h"(hi) : "f"(w), "f"(z));
    return (uint32_t)lo | ((uint32_t)hi << 16);
}
__device__ __forceinline__ uint32_t pack_bf16x2(float even, float odd) {
    uint32_t r;   // d.hi = cvt(odd), d.lo = cvt(even)
    asm("cvt.rn.bf16x2.f32 %0, %1, %2;" : "=r"(r) : "f"(odd), "f"(even));
    return r;
}
#define CP16(sa, gp) \
    asm volatile("cp.async.cg.shared.global [%0], [%1], 16;" :: "r"(sa), "l"(gp) : "memory")
#define CP_COMMIT()  asm volatile("cp.async.commit_group;" ::: "memory")
#define CP_WAIT0()   asm volatile("cp.async.wait_group 0;" ::: "memory")

// load one 16KB chunk ([128 rows][128B of K]) of a band into swizzled smem
__device__ __forceinline__ void load_chunk(uint32_t dst, int band, int c, int tid) {
#pragma unroll
    for (int q = 0; q < 4; q++) {
        int lin = tid + q * TPB;             // 0..1023
        int r = lin >> 3, seg = lin & 7;
        CP16(dst + r * 128 + ((seg ^ (r & 7)) << 4),
             &g_X8[(size_t)(band * 128 + r) * D + c * 128 + seg * 16]);
    }
}

__device__ __forceinline__ void decode_tile(int t, int& i, int& j) {
    int rem = t, ii = 0;
    while (rem >= NB - ii) { rem -= NB - ii; ii++; }
    i = ii; j = ii + rem;
}

// ===========================================================================
// Kernel 1: L2-normalize rows -> fp32 + e4m3(x16).  One warp per row.
// ===========================================================================
__global__ void normalize_kernel(const float* __restrict__ X) {
    int row  = blockIdx.x * 8 + (threadIdx.x >> 5);
    int lane = threadIdx.x & 31;
    const float4* src = reinterpret_cast<const float4*>(X + (size_t)row * D);

    float4 v[4];
    float s = 0.0f;
#pragma unroll
    for (int i = 0; i < 4; i++) {
        v[i] = src[i * 32 + lane];
        s += v[i].x*v[i].x + v[i].y*v[i].y + v[i].z*v[i].z + v[i].w*v[i].w;
    }
#pragma unroll
    for (int o = 16; o; o >>= 1) s += __shfl_xor_sync(0xffffffffu, s, o);
    float scale = 1.0f / fmaxf(sqrtf(s), 1e-12f);

    float4* dst = reinterpret_cast<float4*>(g_Xn + (size_t)row * D);
    uint32_t* d8 = reinterpret_cast<uint32_t*>(g_X8 + (size_t)row * D);
#pragma unroll
    for (int i = 0; i < 4; i++) {
        v[i].x *= scale; v[i].y *= scale; v[i].z *= scale; v[i].w *= scale;
        dst[i * 32 + lane] = v[i];
        d8[i * 32 + lane] = pack4_e4m3(16.f * v[i].x, 16.f * v[i].y,
                                       16.f * v[i].z, 16.f * v[i].w);
    }
}

// ===========================================================================
// Kernel 2: symmetric-triangle fp8 GEMM, chunk-pipelined, bf16 C staging,
// row+col top-8 candidate emission, mirrored zero-fill.  2 CTAs/SM.
// ===========================================================================
__global__ __launch_bounds__(TPB, 2) void tile_kernel(float* __restrict__ out) {
    extern __shared__ char smem[];
    const uint32_t sb = smem_u32(smem);
    uint32_t* CsW = reinterpret_cast<uint32_t*>(smem + SM_C);   // [128][64] bf16x2

    const int tid = threadIdx.x, wid = tid >> 5, lane = tid & 31;
    const int wr = wid >> 1, wc = wid & 1;
    const int bid = blockIdx.x;

    // blocked partition: first 8 CTAs get 8 tiles, rest 7  (8*8+288*7=2080)
    const int start = bid * 7 + (bid < 8 ? bid : 8);
    const int cnt   = 7 + (bid < 8 ? 1 : 0);

    // ldmatrix lane mapping (16B seg = 16 fp8 = k16)
    const int grp = lane >> 3, l7 = lane & 7;
    const int a_r = ((grp & 1) << 3) | l7, a_s = grp >> 1;
    const int b_n = ((grp >> 1) << 3) | l7, b_s = grp & 1;

    int i, j;
    decode_tile(start, i, j);
    load_chunk(sb + SM_A0, i, 0, tid);
    load_chunk(sb + SM_B0, j, 0, tid);
    CP_COMMIT();

    for (int u = 0; u < cnt; u++) {
        // ---- zero-fill output blocks (i,j) and mirror (fire & forget) ----
        {
            const float4 z = make_float4(0.f, 0.f, 0.f, 0.f);
#pragma unroll
            for (int q = 0; q < 16; q++) {
                int lin = tid + q * TPB;
                int r = lin >> 5, c4 = lin & 31;
                *reinterpret_cast<float4*>(out + (size_t)(i * 128 + r) * N + j * 128 + c4 * 4) = z;
            }
            if (i != j) {
#pragma unroll
                for (int q = 0; q < 16; q++) {
                    int lin = tid + q * TPB;
                    int r = lin >> 5, c4 = lin & 31;
                    *reinterpret_cast<float4*>(out + (size_t)(j * 128 + r) * N + i * 128 + c4 * 4) = z;
                }
            }
        }

        float acc[2][8][4];
#pragma unroll
        for (int mf = 0; mf < 2; mf++)
#pragma unroll
            for (int nf = 0; nf < 8; nf++)
#pragma unroll
                for (int ri = 0; ri < 4; ri++) acc[mf][nf][ri] = 0.0f;

        for (int kc = 0; kc < 4; kc++) {
            CP_WAIT0();
            __syncthreads();          // chunk kc (parity kc&1) visible

            // prefetch next chunk (crosses tile boundary at kc==3)
            if (kc < 3) {
                uint32_t ap = sb + (((kc + 1) & 1) ? SM_A1 : SM_A0);
                uint32_t bp = sb + (((kc + 1) & 1) ? SM_B1 : SM_B0);
                load_chunk(ap, i, kc + 1, tid);
                load_chunk(bp, j, kc + 1, tid);
                CP_COMMIT();
            } else if (u + 1 < cnt) {
                int ni, nj;
                decode_tile(start + u + 1, ni, nj);
                load_chunk(sb + SM_A0, ni, 0, tid);
                load_chunk(sb + SM_B0, nj, 0, tid);
                CP_COMMIT();
            }

            const uint32_t abase = sb + ((kc & 1) ? SM_A1 : SM_A0);
            const uint32_t bbase = sb + ((kc & 1) ? SM_B1 : SM_B0);

#pragma unroll
            for (int ks = 0; ks < 4; ks++) {
                const int sg = ks * 2;
                uint32_t a0[4], a1[4];
                {
                    int r0 = wr * 32 + a_r;
                    ldsm4(a0, abase + r0 * 128 + (((sg + a_s) ^ (r0 & 7)) << 4));
                    int r1 = r0 + 16;
                    ldsm4(a1, abase + r1 * 128 + (((sg + a_s) ^ (r1 & 7)) << 4));
                }
                uint32_t bfr[4][4];
#pragma unroll
                for (int q = 0; q < 4; q++) {
                    int n = wc * 64 + q * 16 + b_n;
                    ldsm4(bfr[q], bbase + n * 128 + (((sg + b_s) ^ (n & 7)) << 4));
                }
#pragma unroll
                for (int nf = 0; nf < 8; nf++) {
                    mma_fp8(acc[0][nf], a0, &bfr[nf >> 1][(nf & 1) * 2]);
                    mma_fp8(acc[1][nf], a1, &bfr[nf >> 1][(nf & 1) * 2]);
                }
            }
        }

        // ---- stage C as bf16x2 words, XOR-swizzled ----
#pragma unroll
        for (int mf = 0; mf < 2; mf++)
#pragma unroll
            for (int nf = 0; nf < 8; nf++)
#pragma unroll
                for (int rp = 0; rp < 2; rp++) {
                    int r = wr * 32 + mf * 16 + (lane >> 2) + rp * 8;
                    int w = wc * 32 + nf * 4 + (lane & 3);
                    CsW[r * 64 + (w ^ (r & 31))] =
                        pack_bf16x2(acc[mf][nf][rp * 2], acc[mf][nf][rp * 2 + 1]);
                }
        __syncthreads();

        // ---- scans: threads 0-127 rows, 128-255 columns ----
        float tv[RT]; int ti[RT];
#pragma unroll
        for (int q = 0; q < RT; q++) { tv[q] = -1e30f; ti[q] = 0; }

        if (tid < 128) {
            const int r = tid, rx = r & 31;
            const uint32_t* wrow = CsW + r * 64;
            for (int w = 0; w < 64; w++) {
                uint32_t word = wrow[w ^ rx];
                float v0 = __uint_as_float(word << 16);
                float v1 = __uint_as_float(word & 0xFFFF0000u);
                if (v0 > tv[RT - 1]) {
                    tv[RT - 1] = v0; ti[RT - 1] = j * 128 + 2 * w;
#pragma unroll
                    for (int p = RT - 1; p > 0; p--)
                        if (tv[p] > tv[p - 1]) {
                            float fv = tv[p]; tv[p] = tv[p - 1]; tv[p - 1] = fv;
                            int   fi = ti[p]; ti[p] = ti[p - 1]; ti[p - 1] = fi;
                        }
                }
                if (v1 > tv[RT - 1]) {
                    tv[RT - 1] = v1; ti[RT - 1] = j * 128 + 2 * w + 1;
#pragma unroll
                    for (int p = RT - 1; p > 0; p--)
                        if (tv[p] > tv[p - 1]) {
                            float fv = tv[p]; tv[p] = tv[p - 1]; tv[p - 1] = fv;
                            int   fi = ti[p]; ti[p] = ti[p - 1]; ti[p - 1] = fi;
                        }
                }
            }
            float2* dst = &g_cand[((size_t)(i * 128 + r) * 64 + j) * 8];
#pragma unroll
            for (int q = 0; q < RT; q++)
                dst[q] = make_float2(tv[q], __int_as_float(ti[q]));
        } else if (i != j) {
            const int c = tid - 128, w0 = c >> 1;
            const bool odd = c & 1;
            for (int r = 0; r < 128; r++) {
                uint32_t word = CsW[r * 64 + (w0 ^ (r & 31))];
                float v = odd ? __uint_as_float(word & 0xFFFF0000u)
                              : __uint_as_float(word << 16);
                if (v > tv[RT - 1]) {
                    tv[RT - 1] = v; ti[RT - 1] = i * 128 + r;
#pragma unroll
                    for (int p = RT - 1; p > 0; p--)
                        if (tv[p] > tv[p - 1]) {
                            float fv = tv[p]; tv[p] = tv[p - 1]; tv[p - 1] = fv;
                            int   fi = ti[p]; ti[p] = ti[p - 1]; ti[p - 1] = fi;
                        }
                }
            }
            float2* dst = &g_cand[((size_t)(j * 128 + c) * 64 + i) * 8];
#pragma unroll
            for (int q = 0; q < RT; q++)
                dst[q] = make_float2(tv[q], __int_as_float(ti[q]));
        }

        if (u + 1 < cnt) decode_tile(start + u + 1, i, j);
        // Cs reuse is protected by the 4 per-chunk __syncthreads of next tile
    }
}

// ===========================================================================
// Kernel 3: per-row merge of 64 sorted 8-lists -> top-12, exact fp32 rescore,
// top-5 (jax tie rule), softmax, scatter.  One warp per row.
// ===========================================================================
__global__ __launch_bounds__(256) void merge_rescore(float* __restrict__ out) {
    const int wid = threadIdx.x >> 5, lane = threadIdx.x & 31;
    const int row = blockIdx.x * 8 + wid;

    const float2* base = g_cand + (size_t)row * 512;
    int h0 = 0, h1 = 0;
    float2 e;
    e = base[lane * 8];        float cv0 = e.x; int ci0 = __float_as_int(e.y);
    e = base[(lane + 32) * 8]; float cv1 = e.x; int ci1 = __float_as_int(e.y);

    int selidx[SEL];
#pragma unroll
    for (int it = 0; it < SEL; it++) {
        bool p0 = (cv0 > cv1) || (cv0 == cv1 && ci0 <= ci1);
        float v = p0 ? cv0 : cv1;
        int  ix = p0 ? ci0 : ci1;
        float bv = v; int bi = ix, bl = lane;
#pragma unroll
        for (int o = 16; o; o >>= 1) {
            float ov = __shfl_xor_sync(0xffffffffu, bv, o);
            int   oi = __shfl_xor_sync(0xffffffffu, bi, o);
            int   ol = __shfl_xor_sync(0xffffffffu, bl, o);
            if (ov > bv || (ov == bv && oi < bi)) { bv = ov; bi = oi; bl = ol; }
        }
        selidx[it] = bi;
        if (bl == lane) {
            if (p0) {
                h0++;
                if (h0 < 8) { e = base[lane * 8 + h0]; cv0 = e.x; ci0 = __float_as_int(e.y); }
                else cv0 = -1e30f;
            } else {
                h1++;
                if (h1 < 8) { e = base[(lane + 32) * 8 + h1]; cv1 = e.x; ci1 = __float_as_int(e.y); }
                else cv1 = -1e30f;
            }
        }
    }

    // ---- exact fp32 rescore of the 12 selected ----
    float xr[16];
#pragma unroll
    for (int q = 0; q < 16; q++) xr[q] = g_Xn[(size_t)row * D + q * 32 + lane];

    float myv = -1e30f; int myi = 0x7fffffff;
#pragma unroll
    for (int c = 0; c < SEL; c++) {
        int idx = selidx[c];
        const float* Xc = g_Xn + (size_t)idx * D;
        float s = 0.f;
#pragma unroll
        for (int q = 0; q < 16; q++) s = fmaf(xr[q], Xc[q * 32 + lane], s);
#pragma unroll
        for (int o = 16; o; o >>= 1) s += __shfl_xor_sync(0xffffffffu, s, o);
        if (lane == c) { myv = s; myi = idx; }
    }

    float sv[5]; int si[5];
#pragma unroll
    for (int r5 = 0; r5 < 5; r5++) {
        float v = myv; int ix = myi;
#pragma unroll
        for (int o = 16; o; o >>= 1) {
            float ov = __shfl_xor_sync(0xffffffffu, v, o);
            int   oi = __shfl_xor_sync(0xffffffffu, ix, o);
            if (ov > v || (ov == v && oi < ix)) { v = ov; ix = oi; }
        }
        sv[r5] = v; si[r5] = ix;
        if (myi == ix) { myv = -1e30f; myi = 0x7fffffff; }
    }

    if (lane == 0) {
        float m = sv[0];
        float e0 = expf((sv[0] - m) * TEMP_INV);
        float e1 = expf((sv[1] - m) * TEMP_INV);
        float e2 = expf((sv[2] - m) * TEMP_INV);
        float e3 = expf((sv[3] - m) * TEMP_INV);
        float e4 = expf((sv[4] - m) * TEMP_INV);
        float inv = 1.0f / (e0 + e1 + e2 + e3 + e4);
        float* o = out + (size_t)row * N;
        o[si[0]] = e0 * inv; o[si[1]] = e1 * inv; o[si[2]] = e2 * inv;
        o[si[3]] = e3 * inv; o[si[4]] = e4 * inv;
    }
}

// ===========================================================================
extern "C" void kernel_launch(void* const* d_in, const int* in_sizes, int n_in,
                              void* d_out, int out_size) {
    (void)in_sizes; (void)n_in; (void)out_size;
    const float* X   = (const float*)d_in[0];
    float*       out = (float*)d_out;

    cudaFuncSetAttribute(tile_kernel, cudaFuncAttributeMaxDynamicSharedMemorySize, SMEM_TOTAL);

    normalize_kernel<<<N / 8, 256>>>(X);
    tile_kernel<<<G2, TPB, SMEM_TOTAL>>>(out);
    merge_rescore<<<N / 8, 256>>>(out);
}

// round 9
// speedup vs baseline: 8.3168x; 1.0338x over previous
#include <cuda_runtime.h>
#include <cuda_bf16.h>
#include <cstdint>
#include <math.h>

#define N 8192
#define D 512
#define TEMP_INV 10.0f

#define NB    64          // 128-row bands
#define NTT   2080        // NB*(NB+1)/2 upper-triangle tiles
#define G2    296         // CTAs (2 per SM)
#define TPB   256
#define RT    8           // per-slot top-K kept
#define SEL   12          // candidates rescored exactly
#define CSTR  68          // C staging row stride in words (64 + 4 pad)

// ---- device scratch (static; no allocations allowed) ----
__device__ float    g_Xn[N * D];        // 16 MB fp32 normalized (exact rescore)
__device__ uint8_t  g_X8[N * D];        // 4 MB e4m3 normalized*16 (GEMM)
__device__ float2   g_cand[N * 64 * 8]; // candidate table (val, idx)
__device__ int      g_ticket;           // work-stealing counter

// ---- SMEM: A dbl 2x16K | B dbl 2x16K | C bf16 (128 x 68 words) ----
#define SM_A0  0
#define SM_A1  16384
#define SM_B0  32768
#define SM_B1  49152
#define SM_C   65536
#define SMEM_TOTAL (SM_C + 128 * CSTR * 4)   // 100352 B

// ================= helpers =================
__device__ __forceinline__ uint32_t smem_u32(const void* p) {
    uint32_t a;
    asm("{ .reg .u64 t; cvta.to.shared.u64 t, %1; cvt.u32.u64 %0, t; }" : "=r"(a) : "l"(p));
    return a;
}
__device__ __forceinline__ void ldsm4(uint32_t* r, uint32_t addr) {
    asm volatile("ldmatrix.sync.aligned.m8n8.x4.shared.b16 {%0,%1,%2,%3}, [%4];"
                 : "=r"(r[0]), "=r"(r[1]), "=r"(r[2]), "=r"(r[3]) : "r"(addr));
}
__device__ __forceinline__ void mma_fp8(float* c, const uint32_t* a, const uint32_t* b) {
    asm volatile("mma.sync.aligned.m16n8k32.row.col.f32.e4m3.e4m3.f32 "
                 "{%0,%1,%2,%3}, {%4,%5,%6,%7}, {%8,%9}, {%0,%1,%2,%3};"
                 : "+f"(c[0]), "+f"(c[1]), "+f"(c[2]), "+f"(c[3])
                 : "r"(a[0]), "r"(a[1]), "r"(a[2]), "r"(a[3]), "r"(b[0]), "r"(b[1]));
}
__device__ __forceinline__ uint32_t pack4_e4m3(float x, float y, float z, float w) {
    uint16_t lo, hi;
    asm("cvt.rn.satfinite.e4m3x2.f32 %0, %1, %2;" : "=h"(lo) : "f"(y), "f"(x));
    asm("cvt.rn.satfinite.e4m3x2.f32 %0, %1, %2;" : "=h"(hi) : "f"(w), "f"(z));
    return (uint32_t)lo | ((uint32_t)hi << 16);
}
__device__ __forceinline__ uint32_t pack_bf16x2(float even, float odd) {
    uint32_t r;   // hi = odd, lo = even
    asm("cvt.rn.bf16x2.f32 %0, %1, %2;" : "=r"(r) : "f"(odd), "f"(even));
    return r;
}
__device__ __forceinline__ float bflo(uint32_t w) { return __uint_as_float(w << 16); }
__device__ __forceinline__ float bfhi(uint32_t w) { return __uint_as_float(w & 0xFFFF0000u); }
__device__ __forceinline__ __nv_bfloat162 as_bf2(uint32_t w) {
    return *reinterpret_cast<const __nv_bfloat162*>(&w);
}
#define CP16(sa, gp) \
    asm volatile("cp.async.cg.shared.global [%0], [%1], 16;" :: "r"(sa), "l"(gp) : "memory")
#define CP_COMMIT()  asm volatile("cp.async.commit_group;" ::: "memory")
#define CP_WAIT0()   asm volatile("cp.async.wait_group 0;" ::: "memory")

// load one 16KB chunk ([128 rows][128B of K]) of a band into swizzled smem
__device__ __forceinline__ void load_chunk(uint32_t dst, int band, int c, int tid) {
#pragma unroll
    for (int q = 0; q < 4; q++) {
        int lin = tid + q * TPB;
        int r = lin >> 3, seg = lin & 7;
        CP16(dst + r * 128 + ((seg ^ (r & 7)) << 4),
             &g_X8[(size_t)(band * 128 + r) * D + c * 128 + seg * 16]);
    }
}

__device__ __forceinline__ void decode_tile(int t, int& i, int& j) {
    int rem = t, ii = 0;
    while (rem >= NB - ii) { rem -= NB - ii; ii++; }
    i = ii; j = ii + rem;
}

// ===========================================================================
// Kernel 1: L2-normalize rows -> fp32 + e4m3(x16); resets ticket.
// ===========================================================================
__global__ void normalize_kernel(const float* __restrict__ X) {
    if (blockIdx.x == 0 && threadIdx.x == 0) g_ticket = 0;

    int row  = blockIdx.x * 8 + (threadIdx.x >> 5);
    int lane = threadIdx.x & 31;
    const float4* src = reinterpret_cast<const float4*>(X + (size_t)row * D);

    float4 v[4];
    float s = 0.0f;
#pragma unroll
    for (int i = 0; i < 4; i++) {
        v[i] = src[i * 32 + lane];
        s += v[i].x*v[i].x + v[i].y*v[i].y + v[i].z*v[i].z + v[i].w*v[i].w;
    }
#pragma unroll
    for (int o = 16; o; o >>= 1) s += __shfl_xor_sync(0xffffffffu, s, o);
    float scale = 1.0f / fmaxf(sqrtf(s), 1e-12f);

    float4* dst = reinterpret_cast<float4*>(g_Xn + (size_t)row * D);
    uint32_t* d8 = reinterpret_cast<uint32_t*>(g_X8 + (size_t)row * D);
#pragma unroll
    for (int i = 0; i < 4; i++) {
        v[i].x *= scale; v[i].y *= scale; v[i].z *= scale; v[i].w *= scale;
        dst[i * 32 + lane] = v[i];
        d8[i * 32 + lane] = pack4_e4m3(16.f * v[i].x, 16.f * v[i].y,
                                       16.f * v[i].z, 16.f * v[i].w);
    }
}

// ===========================================================================
// Kernel 2: symmetric-triangle fp8 GEMM, work-stealing tiles, SIMD-max scans.
// ===========================================================================
__global__ __launch_bounds__(TPB, 2) void tile_kernel(float* __restrict__ out) {
    extern __shared__ char smem[];
    __shared__ int s_next;
    const uint32_t sb = smem_u32(smem);
    uint32_t* CsW = reinterpret_cast<uint32_t*>(smem + SM_C);   // [128][CSTR] bf16x2

    const int tid = threadIdx.x, wid = tid >> 5, lane = tid & 31;
    const int wr = wid >> 1, wc = wid & 1;

    // ldmatrix lane mapping (16B seg = 16 fp8 = k16)
    const int grp = lane >> 3, l7 = lane & 7;
    const int a_r = ((grp & 1) << 3) | l7, a_s = grp >> 1;
    const int b_n = ((grp >> 1) << 3) | l7, b_s = grp & 1;

    if (tid == 0) s_next = atomicAdd(&g_ticket, 1);
    __syncthreads();
    int t = s_next;
    int i = 0, j = 0;
    if (t < NTT) {
        decode_tile(t, i, j);
        load_chunk(sb + SM_A0, i, 0, tid);
        load_chunk(sb + SM_B0, j, 0, tid);
        CP_COMMIT();
    }

    while (t < NTT) {
        // ---- zero-fill output blocks (i,j) and mirror (fire & forget) ----
        {
            const float4 z = make_float4(0.f, 0.f, 0.f, 0.f);
#pragma unroll
            for (int q = 0; q < 16; q++) {
                int lin = tid + q * TPB;
                int r = lin >> 5, c4 = lin & 31;
                *reinterpret_cast<float4*>(out + (size_t)(i * 128 + r) * N + j * 128 + c4 * 4) = z;
            }
            if (i != j) {
#pragma unroll
                for (int q = 0; q < 16; q++) {
                    int lin = tid + q * TPB;
                    int r = lin >> 5, c4 = lin & 31;
                    *reinterpret_cast<float4*>(out + (size_t)(j * 128 + r) * N + i * 128 + c4 * 4) = z;
                }
            }
        }

        float acc[2][8][4];
#pragma unroll
        for (int mf = 0; mf < 2; mf++)
#pragma unroll
            for (int nf = 0; nf < 8; nf++)
#pragma unroll
                for (int ri = 0; ri < 4; ri++) acc[mf][nf][ri] = 0.0f;

        int nt = t, ni = i, nj = j;
        for (int kc = 0; kc < 4; kc++) {
            CP_WAIT0();
            __syncthreads();          // chunk kc (parity kc&1) visible; prior epilogue done

            if (kc == 0 && tid == 0) s_next = atomicAdd(&g_ticket, 1);

            if (kc < 3) {
                uint32_t ap = sb + (((kc + 1) & 1) ? SM_A1 : SM_A0);
                uint32_t bp = sb + (((kc + 1) & 1) ? SM_B1 : SM_B0);
                load_chunk(ap, i, kc + 1, tid);
                load_chunk(bp, j, kc + 1, tid);
                CP_COMMIT();
            } else {
                nt = s_next;          // published by kc==1..3 barriers
                if (nt < NTT) {
                    decode_tile(nt, ni, nj);
                    load_chunk(sb + SM_A0, ni, 0, tid);
                    load_chunk(sb + SM_B0, nj, 0, tid);
                    CP_COMMIT();
                }
            }

            const uint32_t abase = sb + ((kc & 1) ? SM_A1 : SM_A0);
            const uint32_t bbase = sb + ((kc & 1) ? SM_B1 : SM_B0);

#pragma unroll
            for (int ks = 0; ks < 4; ks++) {
                const int sg = ks * 2;
                uint32_t a0[4], a1[4];
                {
                    int r0 = wr * 32 + a_r;
                    ldsm4(a0, abase + r0 * 128 + (((sg + a_s) ^ (r0 & 7)) << 4));
                    int r1 = r0 + 16;
                    ldsm4(a1, abase + r1 * 128 + (((sg + a_s) ^ (r1 & 7)) << 4));
                }
                uint32_t bfr[4][4];
#pragma unroll
                for (int q = 0; q < 4; q++) {
                    int n = wc * 64 + q * 16 + b_n;
                    ldsm4(bfr[q], bbase + n * 128 + (((sg + b_s) ^ (n & 7)) << 4));
                }
#pragma unroll
                for (int nf = 0; nf < 8; nf++) {
                    mma_fp8(acc[0][nf], a0, &bfr[nf >> 1][(nf & 1) * 2]);
                    mma_fp8(acc[1][nf], a1, &bfr[nf >> 1][(nf & 1) * 2]);
                }
            }
        }

        // ---- stage C: word w' = wc*32 + (lane&3)*8 + nf  (nf-contiguous) ----
        // word holds cols  c = wc*64 + nf*8 + (lane&3)*2  (lo)  and c+1 (hi)
#pragma unroll
        for (int mf = 0; mf < 2; mf++)
#pragma unroll
            for (int rp = 0; rp < 2; rp++) {
                int r = wr * 32 + mf * 16 + (lane >> 2) + rp * 8;
                uint32_t* dst = CsW + r * CSTR + wc * 32 + (lane & 3) * 8;
                uint4 w0, w1;
                w0.x = pack_bf16x2(acc[mf][0][rp*2], acc[mf][0][rp*2+1]);
                w0.y = pack_bf16x2(acc[mf][1][rp*2], acc[mf][1][rp*2+1]);
                w0.z = pack_bf16x2(acc[mf][2][rp*2], acc[mf][2][rp*2+1]);
                w0.w = pack_bf16x2(acc[mf][3][rp*2], acc[mf][3][rp*2+1]);
                w1.x = pack_bf16x2(acc[mf][4][rp*2], acc[mf][4][rp*2+1]);
                w1.y = pack_bf16x2(acc[mf][5][rp*2], acc[mf][5][rp*2+1]);
                w1.z = pack_bf16x2(acc[mf][6][rp*2], acc[mf][6][rp*2+1]);
                w1.w = pack_bf16x2(acc[mf][7][rp*2], acc[mf][7][rp*2+1]);
                *reinterpret_cast<uint4*>(dst)     = w0;
                *reinterpret_cast<uint4*>(dst + 4) = w1;
            }
        __syncthreads();

        // ---- scans with SIMD-max fast path ----
        float tv[RT]; int ti[RT];
#pragma unroll
        for (int q = 0; q < RT; q++) { tv[q] = -1e30f; ti[q] = 0; }

        if (tid < 128) {
            // row scan: row r, 16 groups of 4 words (8 values)
            const int r = tid;
            const uint32_t* base = CsW + r * CSTR;
            for (int g = 0; g < 16; g++) {
                uint4 qw = *reinterpret_cast<const uint4*>(base + 4 * g);
                __nv_bfloat162 m = __hmax2(__hmax2(as_bf2(qw.x), as_bf2(qw.y)),
                                           __hmax2(as_bf2(qw.z), as_bf2(qw.w)));
                float mx = fmaxf(__low2float(m), __high2float(m));
                if (mx > tv[RT - 1]) {
                    uint32_t ws[4] = {qw.x, qw.y, qw.z, qw.w};
#pragma unroll
                    for (int k = 0; k < 4; k++) {
                        int w = 4 * g + k;
                        int c = ((w >> 5) << 6) + ((w & 7) << 3) + (((w >> 3) & 3) << 1);
                        float v0 = bflo(ws[k]), v1 = bfhi(ws[k]);
#pragma unroll
                        for (int h = 0; h < 2; h++) {
                            float v = h ? v1 : v0;
                            if (v > tv[RT - 1]) {
                                tv[RT - 1] = v; ti[RT - 1] = j * 128 + c + h;
#pragma unroll
                                for (int p = RT - 1; p > 0; p--)
                                    if (tv[p] > tv[p - 1]) {
                                        float fv = tv[p]; tv[p] = tv[p-1]; tv[p-1] = fv;
                                        int   fi = ti[p]; ti[p] = ti[p-1]; ti[p-1] = fi;
                                    }
                            }
                        }
                    }
                }
            }
            float2* dst = &g_cand[((size_t)(i * 128 + r) * 64 + j) * 8];
#pragma unroll
            for (int q = 0; q < RT; q++)
                dst[q] = make_float2(tv[q], __int_as_float(ti[q]));
        } else if (i != j) {
            // col scan: col c, 32 groups of 4 rows
            const int c = tid - 128;
            const int cc = c & 63;
            const int wprime = ((c >> 6) << 5) + (((cc >> 1) & 3) << 3) + (cc >> 3);
            const bool odd = cc & 1;
            const uint32_t* base = CsW + wprime;
            for (int g = 0; g < 32; g++) {
                uint32_t w0 = base[(4*g + 0) * CSTR];
                uint32_t w1 = base[(4*g + 1) * CSTR];
                uint32_t w2 = base[(4*g + 2) * CSTR];
                uint32_t w3 = base[(4*g + 3) * CSTR];
                float v0 = odd ? bfhi(w0) : bflo(w0);
                float v1 = odd ? bfhi(w1) : bflo(w1);
                float v2 = odd ? bfhi(w2) : bflo(w2);
                float v3 = odd ? bfhi(w3) : bflo(w3);
                float mx = fmaxf(fmaxf(v0, v1), fmaxf(v2, v3));
                if (mx > tv[RT - 1]) {
                    float vs[4] = {v0, v1, v2, v3};
#pragma unroll
                    for (int k = 0; k < 4; k++) {
                        float v = vs[k];
                        if (v > tv[RT - 1]) {
                            tv[RT - 1] = v; ti[RT - 1] = i * 128 + 4*g + k;
#pragma unroll
                            for (int p = RT - 1; p > 0; p--)
                                if (tv[p] > tv[p - 1]) {
                                    float fv = tv[p]; tv[p] = tv[p-1]; tv[p-1] = fv;
                                    int   fi = ti[p]; ti[p] = ti[p-1]; ti[p-1] = fi;
                                }
                        }
                    }
                }
            }
            float2* dst = &g_cand[((size_t)(j * 128 + c) * 64 + i) * 8];
#pragma unroll
            for (int q = 0; q < RT; q++)
                dst[q] = make_float2(tv[q], __int_as_float(ti[q]));
        }

        t = nt; i = ni; j = nj;
        // Cs reuse protected by next tile's mainloop barriers
    }
}

// ===========================================================================
// Kernel 3: per-row merge of 64 sorted 8-lists -> top-12, exact fp32 rescore,
// top-5 (jax tie rule), softmax, scatter.  One warp per row.
// ===========================================================================
__global__ __launch_bounds__(256) void merge_rescore(float* __restrict__ out) {
    const int wid = threadIdx.x >> 5, lane = threadIdx.x & 31;
    const int row = blockIdx.x * 8 + wid;

    const float2* base = g_cand + (size_t)row * 512;
    int h0 = 0, h1 = 0;
    float2 e;
    e = base[lane * 8];        float cv0 = e.x; int ci0 = __float_as_int(e.y);
    e = base[(lane + 32) * 8]; float cv1 = e.x; int ci1 = __float_as_int(e.y);

    int selidx[SEL];
#pragma unroll
    for (int it = 0; it < SEL; it++) {
        bool p0 = (cv0 > cv1) || (cv0 == cv1 && ci0 <= ci1);
        float v = p0 ? cv0 : cv1;
        int  ix = p0 ? ci0 : ci1;
        float bv = v; int bi = ix, bl = lane;
#pragma unroll
        for (int o = 16; o; o >>= 1) {
            float ov = __shfl_xor_sync(0xffffffffu, bv, o);
            int   oi = __shfl_xor_sync(0xffffffffu, bi, o);
            int   ol = __shfl_xor_sync(0xffffffffu, bl, o);
            if (ov > bv || (ov == bv && oi < bi)) { bv = ov; bi = oi; bl = ol; }
        }
        selidx[it] = bi;
        if (bl == lane) {
            if (p0) {
                h0++;
                if (h0 < 8) { e = base[lane * 8 + h0]; cv0 = e.x; ci0 = __float_as_int(e.y); }
                else cv0 = -1e30f;
            } else {
                h1++;
                if (h1 < 8) { e = base[(lane + 32) * 8 + h1]; cv1 = e.x; ci1 = __float_as_int(e.y); }
                else cv1 = -1e30f;
            }
        }
    }

    // ---- exact fp32 rescore of the 12 selected ----
    float xr[16];
#pragma unroll
    for (int q = 0; q < 16; q++) xr[q] = g_Xn[(size_t)row * D + q * 32 + lane];

    float myv = -1e30f; int myi = 0x7fffffff;
#pragma unroll
    for (int c = 0; c < SEL; c++) {
        int idx = selidx[c];
        const float* Xc = g_Xn + (size_t)idx * D;
        float s = 0.f;
#pragma unroll
        for (int q = 0; q < 16; q++) s = fmaf(xr[q], Xc[q * 32 + lane], s);
#pragma unroll
        for (int o = 16; o; o >>= 1) s += __shfl_xor_sync(0xffffffffu, s, o);
        if (lane == c) { myv = s; myi = idx; }
    }

    float sv[5]; int si[5];
#pragma unroll
    for (int r5 = 0; r5 < 5; r5++) {
        float v = myv; int ix = myi;
#pragma unroll
        for (int o = 16; o; o >>= 1) {
            float ov = __shfl_xor_sync(0xffffffffu, v, o);
            int   oi = __shfl_xor_sync(0xffffffffu, ix, o);
            if (ov > v || (ov == v && oi < ix)) { v = ov; ix = oi; }
        }
        sv[r5] = v; si[r5] = ix;
        if (myi == ix) { myv = -1e30f; myi = 0x7fffffff; }
    }

    if (lane == 0) {
        float m = sv[0];
        float e0 = expf((sv[0] - m) * TEMP_INV);
        float e1 = expf((sv[1] - m) * TEMP_INV);
        float e2 = expf((sv[2] - m) * TEMP_INV);
        float e3 = expf((sv[3] - m) * TEMP_INV);
        float e4 = expf((sv[4] - m) * TEMP_INV);
        float inv = 1.0f / (e0 + e1 + e2 + e3 + e4);
        float* o = out + (size_t)row * N;
        o[si[0]] = e0 * inv; o[si[1]] = e1 * inv; o[si[2]] = e2 * inv;
        o[si[3]] = e3 * inv; o[si[4]] = e4 * inv;
    }
}

// ===========================================================================
extern "C" void kernel_launch(void* const* d_in, const int* in_sizes, int n_in,
                              void* d_out, int out_size) {
    (void)in_sizes; (void)n_in; (void)out_size;
    const float* X   = (const float*)d_in[0];
    float*       out = (float*)d_out;

    cudaFuncSetAttribute(tile_kernel, cudaFuncAttributeMaxDynamicSharedMemorySize, SMEM_TOTAL);

    normalize_kernel<<<N / 8, 256>>>(X);
    tile_kernel<<<G2, TPB, SMEM_TOTAL>>>(out);
    merge_rescore<<<N / 8, 256>>>(out);
}